// round 3
// baseline (speedup 1.0000x reference)
#include <cuda_runtime.h>
#include <math.h>

// Problem constants
#define BATCH 512
#define SEQ   256
#define CDIM  384
#define HDIM  384
#define M_TOTAL (BATCH * SEQ)   // 131072

// ---------------------------------------------------------------------------
// Device scratch (static: runtime allocation is forbidden)
// ---------------------------------------------------------------------------
__device__ float g_q[(size_t)M_TOTAL * HDIM];
__device__ float g_k[(size_t)M_TOTAL * HDIM];
__device__ float g_v[(size_t)M_TOTAL * HDIM];

// ---------------------------------------------------------------------------
// Packed fp32x2 helpers (Blackwell FFMA2 — only reachable via PTX)
// ---------------------------------------------------------------------------
__device__ __forceinline__ unsigned long long pk2(float x, float y) {
    unsigned long long r;
    asm("mov.b64 %0, {%1, %2};" : "=l"(r) : "f"(x), "f"(y));
    return r;
}
__device__ __forceinline__ void upk2(unsigned long long v, float& x, float& y) {
    asm("mov.b64 {%0, %1}, %2;" : "=f"(x), "=f"(y) : "l"(v));
}
__device__ __forceinline__ void fma2(unsigned long long& d,
                                     unsigned long long a,
                                     unsigned long long b) {
    asm("fma.rn.f32x2 %0, %1, %2, %3;" : "=l"(d) : "l"(a), "l"(b), "l"(d));
}

// ---------------------------------------------------------------------------
// Kernel 1: fused QKV projection.
// C[M,1152] = X[M,384] * [Wq|Wk|Wv], written to g_q/g_k/g_v.
// 128x128x16 tiles, 256 threads, 8x8 microtile, packed f32x2 FMA.
// ---------------------------------------------------------------------------
__global__ __launch_bounds__(256) void qkv_kernel(
    const float* __restrict__ X,
    const float* __restrict__ Wq,
    const float* __restrict__ Wk,
    const float* __restrict__ Wv)
{
    __shared__ float As[16][132];   // [k][m] transposed, padded
    __shared__ float Bs[16][128];   // [k][n]

    const int t   = threadIdx.x;
    const int m0  = blockIdx.x * 128;
    const int n0g = blockIdx.y * 128;
    const int wsel = n0g / HDIM;          // 384 = 3*128 -> block never straddles
    const int n0   = n0g - wsel * HDIM;

    const float* W = (wsel == 0) ? Wq : ((wsel == 1) ? Wk : Wv);
    float* out     = (wsel == 0) ? g_q : ((wsel == 1) ? g_k : g_v);

    const int tx = t & 15;   // 0..15 -> cols tx*8
    const int ty = t >> 4;   // 0..15 -> rows ty*8

    unsigned long long acc[8][4];
    #pragma unroll
    for (int i = 0; i < 8; i++)
        #pragma unroll
        for (int j = 0; j < 4; j++) acc[i][j] = 0ull;

    const int ra = t >> 2;         // 0..63
    const int ca = (t & 3) * 4;    // 0,4,8,12
    const int rb = t >> 5;         // 0..7
    const int cb = (t & 31) * 4;   // 0..124

    for (int k0 = 0; k0 < CDIM; k0 += 16) {
        // Load A tile (128 rows x 16 k), store transposed
        float4 a0 = *(const float4*)(X + (size_t)(m0 + ra) * CDIM + k0 + ca);
        float4 a1 = *(const float4*)(X + (size_t)(m0 + ra + 64) * CDIM + k0 + ca);
        As[ca + 0][ra] = a0.x; As[ca + 1][ra] = a0.y;
        As[ca + 2][ra] = a0.z; As[ca + 3][ra] = a0.w;
        As[ca + 0][ra + 64] = a1.x; As[ca + 1][ra + 64] = a1.y;
        As[ca + 2][ra + 64] = a1.z; As[ca + 3][ra + 64] = a1.w;
        // Load B tile (16 k x 128 n)
        *(float4*)&Bs[rb][cb]     = *(const float4*)(W + (size_t)(k0 + rb) * HDIM + n0 + cb);
        *(float4*)&Bs[rb + 8][cb] = *(const float4*)(W + (size_t)(k0 + rb + 8) * HDIM + n0 + cb);
        __syncthreads();

        #pragma unroll
        for (int k = 0; k < 16; k++) {
            float4 av0 = *(float4*)&As[k][ty * 8];
            float4 av1 = *(float4*)&As[k][ty * 8 + 4];
            float4 bv0 = *(float4*)&Bs[k][tx * 8];
            float4 bv1 = *(float4*)&Bs[k][tx * 8 + 4];
            float a[8] = {av0.x, av0.y, av0.z, av0.w, av1.x, av1.y, av1.z, av1.w};
            unsigned long long bp0 = pk2(bv0.x, bv0.y);
            unsigned long long bp1 = pk2(bv0.z, bv0.w);
            unsigned long long bp2 = pk2(bv1.x, bv1.y);
            unsigned long long bp3 = pk2(bv1.z, bv1.w);
            #pragma unroll
            for (int i = 0; i < 8; i++) {
                unsigned long long ap = pk2(a[i], a[i]);
                fma2(acc[i][0], ap, bp0);
                fma2(acc[i][1], ap, bp1);
                fma2(acc[i][2], ap, bp2);
                fma2(acc[i][3], ap, bp3);
            }
        }
        __syncthreads();
    }

    #pragma unroll
    for (int i = 0; i < 8; i++) {
        float o[8];
        upk2(acc[i][0], o[0], o[1]);
        upk2(acc[i][1], o[2], o[3]);
        upk2(acc[i][2], o[4], o[5]);
        upk2(acc[i][3], o[6], o[7]);
        float* dst = out + (size_t)(m0 + ty * 8 + i) * HDIM + n0 + tx * 8;
        *(float4*)(dst)     = make_float4(o[0], o[1], o[2], o[3]);
        *(float4*)(dst + 4) = make_float4(o[4], o[5], o[6], o[7]);
    }
}

// ---------------------------------------------------------------------------
// Kernel 2: causal attention. One block = (batch b, 64-query tile bq).
// Phase A: S[64][256] = Q Kt (causally pruned per 64-key chunk, f32x2)
// Phase B: in-smem causal softmax (full key row resident)
// Phase C: O[64][384] = P V, chunked over 128 head cols
// ---------------------------------------------------------------------------
#define QCT_STRIDE 65     // QcT[k][row]  (k-major, bank-safe)
#define KC_STRIDE  65     // Kc[key][h]
#define PS_STRIDE  260    // Ps[row][key] (float4-aligned, bank-safe)
#define SMEM_FLOATS 24832 // max(4160+16640, 16640+8192)

__global__ __launch_bounds__(256) void attn_kernel(float* __restrict__ Out)
{
    extern __shared__ float sm[];
    float* QcT = sm;            // [64][65]  (phase A)
    float* Kc  = sm + 4160;     // [256][65] (phase A)
    float* Ps  = sm;            // [64][260] (phase B/C, overlays A)
    float* Vc  = sm + 16640;    // [64][128] (phase C)

    const int t  = threadIdx.x;
    const int bq = blockIdx.x;           // 0..3
    const int b  = blockIdx.y;           // 0..511
    const int q0  = bq * 64;
    const int nkb = bq + 1;              // valid 64-key chunks
    const int Kv  = nkb * 64;            // valid key upper bound
    const float scl = rsqrtf((float)HDIM);

    const int tr = t & 7;      // row group: rows tr + 8*i
    const int tc = t >> 3;     // 0..31

    // ---------------- Phase A: S = Q Kt -----------------------------------
    unsigned long long sp[8][4];
    #pragma unroll
    for (int i = 0; i < 8; i++)
        #pragma unroll
        for (int p = 0; p < 4; p++) sp[i][p] = 0ull;

    const bool act = (tc < nkb * 8);    // warp-uniform (4 tc per warp)

    for (int hc = 0; hc < HDIM; hc += 64) {
        // load Q tile 64x64 -> QcT[k][r]
        #pragma unroll
        for (int rep = 0; rep < 4; rep++) {
            int lin = t + rep * 256;
            int kq  = (lin & 15) << 2;
            int r   = lin >> 4;
            float4 v = *(const float4*)(g_q + (size_t)(b * SEQ + q0 + r) * HDIM + hc + kq);
            QcT[(kq + 0) * QCT_STRIDE + r] = v.x;
            QcT[(kq + 1) * QCT_STRIDE + r] = v.y;
            QcT[(kq + 2) * QCT_STRIDE + r] = v.z;
            QcT[(kq + 3) * QCT_STRIDE + r] = v.w;
        }
        // load K tile (only valid keys) -> Kc[key][h]
        #pragma unroll
        for (int rep = 0; rep < 16; rep++) {
            int lin = t + rep * 256;
            int key = lin >> 4;
            if (key < Kv) {
                int kh = (lin & 15) << 2;
                float4 v = *(const float4*)(g_k + (size_t)(b * SEQ + key) * HDIM + hc + kh);
                Kc[key * KC_STRIDE + kh + 0] = v.x;
                Kc[key * KC_STRIDE + kh + 1] = v.y;
                Kc[key * KC_STRIDE + kh + 2] = v.z;
                Kc[key * KC_STRIDE + kh + 3] = v.w;
            }
        }
        __syncthreads();

        if (act) {
            #pragma unroll
            for (int k = 0; k < 64; k++) {
                float a[8], bb[8];
                #pragma unroll
                for (int i = 0; i < 8; i++) a[i]  = QcT[k * QCT_STRIDE + tr + 8 * i];
                #pragma unroll
                for (int j = 0; j < 8; j++) bb[j] = Kc[(tc * 8 + j) * KC_STRIDE + k];
                unsigned long long bp0 = pk2(bb[0], bb[1]);
                unsigned long long bp1 = pk2(bb[2], bb[3]);
                unsigned long long bp2 = pk2(bb[4], bb[5]);
                unsigned long long bp3 = pk2(bb[6], bb[7]);
                #pragma unroll
                for (int i = 0; i < 8; i++) {
                    unsigned long long ap = pk2(a[i], a[i]);
                    fma2(sp[i][0], ap, bp0);
                    fma2(sp[i][1], ap, bp1);
                    fma2(sp[i][2], ap, bp2);
                    fma2(sp[i][3], ap, bp3);
                }
            }
        }
        __syncthreads();
    }

    // ---------------- Phase B: write S (scaled) + softmax ------------------
    if (act) {
        #pragma unroll
        for (int i = 0; i < 8; i++) {
            float* row = Ps + (size_t)(tr + 8 * i) * PS_STRIDE + tc * 8;
            #pragma unroll
            for (int p = 0; p < 4; p++) {
                float lo, hi;
                upk2(sp[i][p], lo, hi);
                row[2 * p + 0] = lo * scl;
                row[2 * p + 1] = hi * scl;
            }
        }
    }
    __syncthreads();

    {
        const int w = t >> 5, lane = t & 31;
        for (int rr = 0; rr < 8; rr++) {
            int r  = w * 8 + rr;
            int qg = q0 + r;                 // valid keys: 0..qg
            float* row = Ps + (size_t)r * PS_STRIDE;
            float m = -1e30f;
            for (int j = lane; j <= qg; j += 32) m = fmaxf(m, row[j]);
            #pragma unroll
            for (int off = 16; off > 0; off >>= 1)
                m = fmaxf(m, __shfl_xor_sync(0xffffffffu, m, off));
            float s = 0.0f;
            for (int j = lane; j <= qg; j += 32) {
                float e = __expf(row[j] - m);
                row[j] = e;
                s += e;
            }
            #pragma unroll
            for (int off = 16; off > 0; off >>= 1)
                s += __shfl_xor_sync(0xffffffffu, s, off);
            float inv = 1.0f / s;
            for (int j = lane; j < Kv; j += 32)
                row[j] = (j <= qg) ? row[j] * inv : 0.0f;
        }
    }
    __syncthreads();

    // ---------------- Phase C: O = P V -------------------------------------
    const int tc4 = tc;     // cols tc4*4 within 128-col chunk
    for (int vc = 0; vc < HDIM; vc += 128) {
        float o[8][4];
        #pragma unroll
        for (int i = 0; i < 8; i++)
            #pragma unroll
            for (int j = 0; j < 4; j++) o[i][j] = 0.0f;

        for (int kb = 0; kb < nkb; kb++) {
            __syncthreads();   // protect Vc reuse
            #pragma unroll
            for (int rep = 0; rep < 8; rep++) {
                int lin = t + rep * 256;
                int c4  = (lin & 31) << 2;
                int kk  = lin >> 5;
                *(float4*)&Vc[kk * 128 + c4] =
                    *(const float4*)(g_v + (size_t)(b * SEQ + kb * 64 + kk) * HDIM + vc + c4);
            }
            __syncthreads();

            #pragma unroll
            for (int kk4 = 0; kk4 < 64; kk4 += 4) {
                float4 a[8];
                #pragma unroll
                for (int i = 0; i < 8; i++)
                    a[i] = *(float4*)&Ps[(size_t)(tr + 8 * i) * PS_STRIDE + kb * 64 + kk4];
                #pragma unroll
                for (int u = 0; u < 4; u++) {
                    float4 bv = *(float4*)&Vc[(kk4 + u) * 128 + tc4 * 4];
                    #pragma unroll
                    for (int i = 0; i < 8; i++) {
                        float au = (u == 0) ? a[i].x : (u == 1) ? a[i].y
                                 : (u == 2) ? a[i].z : a[i].w;
                        o[i][0] += au * bv.x;
                        o[i][1] += au * bv.y;
                        o[i][2] += au * bv.z;
                        o[i][3] += au * bv.w;
                    }
                }
            }
        }

        #pragma unroll
        for (int i = 0; i < 8; i++) {
            float* dst = Out + (size_t)(b * SEQ + q0 + tr + 8 * i) * HDIM + vc + tc4 * 4;
            *(float4*)dst = make_float4(o[i][0], o[i][1], o[i][2], o[i][3]);
        }
    }
}

// ---------------------------------------------------------------------------
// Launch
// ---------------------------------------------------------------------------
extern "C" void kernel_launch(void* const* d_in, const int* in_sizes, int n_in,
                              void* d_out, int out_size)
{
    const float* x  = (const float*)d_in[0];
    const float* Wq = (const float*)d_in[1];
    const float* Wk = (const float*)d_in[2];
    const float* Wv = (const float*)d_in[3];
    float* out = (float*)d_out;

    qkv_kernel<<<dim3(M_TOTAL / 128, (3 * HDIM) / 128), 256>>>(x, Wq, Wk, Wv);

    const int shbytes = SMEM_FLOATS * 4;   // 99328
    cudaFuncSetAttribute(attn_kernel, cudaFuncAttributeMaxDynamicSharedMemorySize, shbytes);
    attn_kernel<<<dim3(SEQ / 64, BATCH), 256, shbytes>>>(out);
}

// round 5
// speedup vs baseline: 1.6132x; 1.6132x over previous
#include <cuda_runtime.h>
#include <cuda_bf16.h>
#include <math.h>

// Problem constants
#define BATCH 512
#define SEQ   256
#define CDIM  384
#define HDIM  384
#define M_TOTAL (BATCH * SEQ)   // 131072

// ---------------------------------------------------------------------------
// Device scratch (static: runtime allocation is forbidden)
// ---------------------------------------------------------------------------
__device__ float g_q[(size_t)M_TOTAL * HDIM];
__device__ float g_k[(size_t)M_TOTAL * HDIM];
__device__ float g_v[(size_t)M_TOTAL * HDIM];
// bf16 hi/lo split of X (precision-compensated bf16 MMA operands)
__device__ __nv_bfloat16 g_xhi[(size_t)M_TOTAL * CDIM];
__device__ __nv_bfloat16 g_xlo[(size_t)M_TOTAL * CDIM];
// bf16 hi/lo of the three weights, TRANSPOSED to [w][n][k] (B operand k-contig)
__device__ __nv_bfloat16 g_whi[(size_t)3 * HDIM * CDIM];
__device__ __nv_bfloat16 g_wlo[(size_t)3 * HDIM * CDIM];

// ---------------------------------------------------------------------------
// PTX helpers (all portable to plain sm_103 target — NO tcgen05)
// ---------------------------------------------------------------------------
__device__ __forceinline__ unsigned int smem_u32(const void* p) {
    unsigned int a;
    asm("{ .reg .u64 t; cvta.to.shared.u64 t, %1; cvt.u32.u64 %0, t; }" : "=r"(a) : "l"(p));
    return a;
}
__device__ __forceinline__ void cp16(unsigned int dst, const void* src) {
    asm volatile("cp.async.cg.shared.global [%0], [%1], 16;" :: "r"(dst), "l"(src));
}
__device__ __forceinline__ void cp_commit() {
    asm volatile("cp.async.commit_group;" ::: "memory");
}
__device__ __forceinline__ void ldsm_x4(unsigned int* r, unsigned int addr) {
    asm volatile("ldmatrix.sync.aligned.m8n8.x4.shared.b16 {%0,%1,%2,%3}, [%4];"
                 : "=r"(r[0]), "=r"(r[1]), "=r"(r[2]), "=r"(r[3]) : "r"(addr));
}
__device__ __forceinline__ void mma_bf16(float* c, const unsigned int* a,
                                         const unsigned int* b) {
    asm volatile("mma.sync.aligned.m16n8k16.row.col.f32.bf16.bf16.f32 "
                 "{%0,%1,%2,%3}, {%4,%5,%6,%7}, {%8,%9}, {%0,%1,%2,%3};"
                 : "+f"(c[0]), "+f"(c[1]), "+f"(c[2]), "+f"(c[3])
                 : "r"(a[0]), "r"(a[1]), "r"(a[2]), "r"(a[3]), "r"(b[0]), "r"(b[1]));
}

// Packed fp32x2 helpers (for the fp32 attention kernel)
__device__ __forceinline__ unsigned long long pk2(float x, float y) {
    unsigned long long r;
    asm("mov.b64 %0, {%1, %2};" : "=l"(r) : "f"(x), "f"(y));
    return r;
}
__device__ __forceinline__ void upk2(unsigned long long v, float& x, float& y) {
    asm("mov.b64 {%0, %1}, %2;" : "=f"(x), "=f"(y) : "l"(v));
}
__device__ __forceinline__ void fma2(unsigned long long& d,
                                     unsigned long long a,
                                     unsigned long long b) {
    asm("fma.rn.f32x2 %0, %1, %2, %3;" : "=l"(d) : "l"(a), "l"(b), "l"(d));
}

// ---------------------------------------------------------------------------
// Prepass 1: X fp32 -> bf16 hi/lo
// ---------------------------------------------------------------------------
__global__ __launch_bounds__(256) void cvt_x_kernel(const float* __restrict__ X)
{
    size_t i = (size_t)blockIdx.x * 256 + threadIdx.x;   // over M*C/4
    float4 v = ((const float4*)X)[i];
    __nv_bfloat16 h0 = __float2bfloat16(v.x);
    __nv_bfloat16 h1 = __float2bfloat16(v.y);
    __nv_bfloat16 h2 = __float2bfloat16(v.z);
    __nv_bfloat16 h3 = __float2bfloat16(v.w);
    __nv_bfloat16 l0 = __float2bfloat16(v.x - __bfloat162float(h0));
    __nv_bfloat16 l1 = __float2bfloat16(v.y - __bfloat162float(h1));
    __nv_bfloat16 l2 = __float2bfloat16(v.z - __bfloat162float(h2));
    __nv_bfloat16 l3 = __float2bfloat16(v.w - __bfloat162float(h3));
    __nv_bfloat162* dh = (__nv_bfloat162*)(g_xhi + 4 * i);
    __nv_bfloat162* dl = (__nv_bfloat162*)(g_xlo + 4 * i);
    dh[0] = __halves2bfloat162(h0, h1);
    dh[1] = __halves2bfloat162(h2, h3);
    dl[0] = __halves2bfloat162(l0, l1);
    dl[1] = __halves2bfloat162(l2, l3);
}

// ---------------------------------------------------------------------------
// Prepass 2: W fp32 [k][n] -> transposed bf16 hi/lo [w][n][k]
// ---------------------------------------------------------------------------
__global__ __launch_bounds__(256) void cvt_w_kernel(const float* __restrict__ Wq,
                                                    const float* __restrict__ Wk,
                                                    const float* __restrict__ Wv)
{
    int i = blockIdx.x * 256 + threadIdx.x;     // < 3*384*384
    int w = i / (CDIM * HDIM);
    int r = i - w * (CDIM * HDIM);
    int k = r / HDIM;
    int n = r - k * HDIM;
    const float* W = (w == 0) ? Wq : ((w == 1) ? Wk : Wv);
    float v = W[(size_t)k * HDIM + n];
    __nv_bfloat16 h = __float2bfloat16(v);
    size_t o = ((size_t)w * HDIM + n) * CDIM + k;
    g_whi[o] = h;
    g_wlo[o] = __float2bfloat16(v - __bfloat162float(h));
}

// ---------------------------------------------------------------------------
// Kernel: QKV GEMM via mma.sync (fallback HMMA path; tcgen05 PTX is rejected
// by this toolchain's non-'a' target).
// CTA tile 128(M) x 128(N), K chunks of 64, double-buffered cp.async.
// 8 warps as 4m x 2n -> warp tile 32x64. D = Ahi*Bhi + Ahi*Blo + Alo*Bhi.
// Smem per stage: Ahi|Alo|Bhi|Blo, each 128 rows x 144B (72 bf16, padded).
// ---------------------------------------------------------------------------
#define ROWB   144            // padded row stride in bytes (72 bf16)
#define TILE_B (128 * ROWB)   // 18432 bytes per operand tile
#define STG_B  (4 * TILE_B)   // 73728 bytes per stage
#define GEMM_SMEM_BYTES (2 * STG_B)   // 147456
#define NCHUNK 6

__global__ __launch_bounds__(256, 1) void qkv_mma_kernel()
{
    extern __shared__ char smem[];
    const unsigned int sb = smem_u32(smem);
    const int t    = threadIdx.x;
    const int wid  = t >> 5;
    const int lane = t & 31;

    const int nblk = blockIdx.x;           // 0..8
    const int w    = nblk / 3;             // weight select
    const int n0   = (nblk - w * 3) * 128; // col offset within weight
    const int m0   = blockIdx.y * 128;

    const __nv_bfloat16* whi = g_whi + (size_t)w * HDIM * CDIM;
    const __nv_bfloat16* wlo = g_wlo + (size_t)w * HDIM * CDIM;

    const int wm = (wid & 3) * 32;         // warp row offset in tile
    const int wn = (wid >> 2) * 64;        // warp col offset in tile

    // ldmatrix per-lane address offsets (within an operand tile)
    const unsigned int a_lane = (unsigned)((lane & 15) * ROWB + (lane >> 4) * 16);
    const unsigned int b_lane = (unsigned)(((lane & 7) + ((lane >> 4) << 3)) * ROWB
                                           + ((lane >> 3) & 1) * 16);

    float acc[2][8][4];
    #pragma unroll
    for (int mt = 0; mt < 2; mt++)
        #pragma unroll
        for (int nt = 0; nt < 8; nt++)
            #pragma unroll
            for (int q = 0; q < 4; q++) acc[mt][nt][q] = 0.0f;

    // ------------- async tile loader: chunk c -> stage buffer -------------
    auto load_chunk = [&](int c, int stage) {
        const unsigned int s0 = sb + stage * STG_B;
        // A hi/lo: 128 rows x 8 x 16B each
        #pragma unroll
        for (int it = 0; it < 4; it++) {
            int s = t + it * 256;
            int r = s >> 3, j = s & 7;
            unsigned int d = (unsigned)(r * ROWB + j * 16);
            const __nv_bfloat16* sh = g_xhi + (size_t)(m0 + r) * CDIM + c * 64 + j * 8;
            const __nv_bfloat16* sl = g_xlo + (size_t)(m0 + r) * CDIM + c * 64 + j * 8;
            cp16(s0 + d, sh);
            cp16(s0 + TILE_B + d, sl);
        }
        // B hi/lo: 128 rows (n) x 8 x 16B each
        #pragma unroll
        for (int it = 0; it < 4; it++) {
            int s = t + it * 256;
            int r = s >> 3, j = s & 7;
            unsigned int d = (unsigned)(r * ROWB + j * 16);
            const __nv_bfloat16* sh = whi + (size_t)(n0 + r) * CDIM + c * 64 + j * 8;
            const __nv_bfloat16* sl = wlo + (size_t)(n0 + r) * CDIM + c * 64 + j * 8;
            cp16(s0 + 2 * TILE_B + d, sh);
            cp16(s0 + 3 * TILE_B + d, sl);
        }
        cp_commit();
    };

    load_chunk(0, 0);

    for (int c = 0; c < NCHUNK; c++) {
        const int stage = c & 1;
        if (c + 1 < NCHUNK) load_chunk(c + 1, stage ^ 1);

        if (c + 1 < NCHUNK)
            asm volatile("cp.async.wait_group 1;" ::: "memory");
        else
            asm volatile("cp.async.wait_group 0;" ::: "memory");
        __syncthreads();

        const unsigned int sa_hi = sb + stage * STG_B;
        const unsigned int sa_lo = sa_hi + TILE_B;
        const unsigned int sb_hi = sa_hi + 2 * TILE_B;
        const unsigned int sb_lo = sa_hi + 3 * TILE_B;

        #pragma unroll
        for (int kk = 0; kk < 4; kk++) {           // 4 x k16 per 64-chunk
            const unsigned int koff = kk * 32;     // 16 bf16 = 32 bytes
            unsigned int Ahi[2][4], Alo[2][4];
            #pragma unroll
            for (int mt = 0; mt < 2; mt++) {
                unsigned int ab = (unsigned)((wm + mt * 16) * ROWB) + koff + a_lane;
                ldsm_x4(Ahi[mt], sa_hi + ab);
                ldsm_x4(Alo[mt], sa_lo + ab);
            }
            #pragma unroll
            for (int nt2 = 0; nt2 < 4; nt2++) {    // 2 n8-tiles per ldmatrix.x4
                unsigned int bb = (unsigned)((wn + nt2 * 16) * ROWB) + koff + b_lane;
                unsigned int Bhi[4], Blo[4];
                ldsm_x4(Bhi, sb_hi + bb);
                ldsm_x4(Blo, sb_lo + bb);
                #pragma unroll
                for (int mt = 0; mt < 2; mt++) {
                    mma_bf16(acc[mt][nt2 * 2 + 0], Ahi[mt], Bhi + 0);
                    mma_bf16(acc[mt][nt2 * 2 + 1], Ahi[mt], Bhi + 2);
                    mma_bf16(acc[mt][nt2 * 2 + 0], Ahi[mt], Blo + 0);
                    mma_bf16(acc[mt][nt2 * 2 + 1], Ahi[mt], Blo + 2);
                    mma_bf16(acc[mt][nt2 * 2 + 0], Alo[mt], Bhi + 0);
                    mma_bf16(acc[mt][nt2 * 2 + 1], Alo[mt], Bhi + 2);
                }
            }
        }
        __syncthreads();
    }

    // ------------- epilogue: c-frag scatter to fp32 output -----------------
    float* outp = (w == 0) ? g_q : ((w == 1) ? g_k : g_v);
    #pragma unroll
    for (int mt = 0; mt < 2; mt++) {
        int r0 = m0 + wm + mt * 16 + (lane >> 2);
        #pragma unroll
        for (int nt = 0; nt < 8; nt++) {
            int cc = n0 + wn + nt * 8 + 2 * (lane & 3);
            *(float2*)(outp + (size_t)r0 * HDIM + cc) =
                make_float2(acc[mt][nt][0], acc[mt][nt][1]);
            *(float2*)(outp + (size_t)(r0 + 8) * HDIM + cc) =
                make_float2(acc[mt][nt][2], acc[mt][nt][3]);
        }
    }
}

// ---------------------------------------------------------------------------
// Kernel: causal attention (unchanged fp32/f32x2 path).
// ---------------------------------------------------------------------------
#define QCT_STRIDE 65
#define KC_STRIDE  65
#define PS_STRIDE  260
#define SMEM_FLOATS 24832

__global__ __launch_bounds__(256) void attn_kernel(float* __restrict__ Out)
{
    extern __shared__ float sm[];
    float* QcT = sm;            // [64][65]  (phase A)
    float* Kc  = sm + 4160;     // [256][65] (phase A)
    float* Ps  = sm;            // [64][260] (phase B/C, overlays A)
    float* Vc  = sm + 16640;    // [64][128] (phase C)

    const int t  = threadIdx.x;
    const int bq = blockIdx.x;           // 0..3
    const int b  = blockIdx.y;           // 0..511
    const int q0  = bq * 64;
    const int nkb = bq + 1;              // valid 64-key chunks
    const int Kv  = nkb * 64;
    const float scl = rsqrtf((float)HDIM);

    const int tr = t & 7;
    const int tc = t >> 3;

    unsigned long long sp[8][4];
    #pragma unroll
    for (int i = 0; i < 8; i++)
        #pragma unroll
        for (int p = 0; p < 4; p++) sp[i][p] = 0ull;

    const bool act = (tc < nkb * 8);

    for (int hc = 0; hc < HDIM; hc += 64) {
        #pragma unroll
        for (int rep = 0; rep < 4; rep++) {
            int lin = t + rep * 256;
            int kq  = (lin & 15) << 2;
            int r   = lin >> 4;
            float4 v = *(const float4*)(g_q + (size_t)(b * SEQ + q0 + r) * HDIM + hc + kq);
            QcT[(kq + 0) * QCT_STRIDE + r] = v.x;
            QcT[(kq + 1) * QCT_STRIDE + r] = v.y;
            QcT[(kq + 2) * QCT_STRIDE + r] = v.z;
            QcT[(kq + 3) * QCT_STRIDE + r] = v.w;
        }
        #pragma unroll
        for (int rep = 0; rep < 16; rep++) {
            int lin = t + rep * 256;
            int key = lin >> 4;
            if (key < Kv) {
                int kh = (lin & 15) << 2;
                float4 v = *(const float4*)(g_k + (size_t)(b * SEQ + key) * HDIM + hc + kh);
                Kc[key * KC_STRIDE + kh + 0] = v.x;
                Kc[key * KC_STRIDE + kh + 1] = v.y;
                Kc[key * KC_STRIDE + kh + 2] = v.z;
                Kc[key * KC_STRIDE + kh + 3] = v.w;
            }
        }
        __syncthreads();

        if (act) {
            #pragma unroll
            for (int k = 0; k < 64; k++) {
                float a[8], bb[8];
                #pragma unroll
                for (int i = 0; i < 8; i++) a[i]  = QcT[k * QCT_STRIDE + tr + 8 * i];
                #pragma unroll
                for (int j = 0; j < 8; j++) bb[j] = Kc[(tc * 8 + j) * KC_STRIDE + k];
                unsigned long long bp0 = pk2(bb[0], bb[1]);
                unsigned long long bp1 = pk2(bb[2], bb[3]);
                unsigned long long bp2 = pk2(bb[4], bb[5]);
                unsigned long long bp3 = pk2(bb[6], bb[7]);
                #pragma unroll
                for (int i = 0; i < 8; i++) {
                    unsigned long long ap = pk2(a[i], a[i]);
                    fma2(sp[i][0], ap, bp0);
                    fma2(sp[i][1], ap, bp1);
                    fma2(sp[i][2], ap, bp2);
                    fma2(sp[i][3], ap, bp3);
                }
            }
        }
        __syncthreads();
    }

    if (act) {
        #pragma unroll
        for (int i = 0; i < 8; i++) {
            float* row = Ps + (size_t)(tr + 8 * i) * PS_STRIDE + tc * 8;
            #pragma unroll
            for (int p = 0; p < 4; p++) {
                float lo, hi;
                upk2(sp[i][p], lo, hi);
                row[2 * p + 0] = lo * scl;
                row[2 * p + 1] = hi * scl;
            }
        }
    }
    __syncthreads();

    {
        const int wq = t >> 5, lane = t & 31;
        for (int rr = 0; rr < 8; rr++) {
            int r  = wq * 8 + rr;
            int qg = q0 + r;
            float* row = Ps + (size_t)r * PS_STRIDE;
            float m = -1e30f;
            for (int j = lane; j <= qg; j += 32) m = fmaxf(m, row[j]);
            #pragma unroll
            for (int off = 16; off > 0; off >>= 1)
                m = fmaxf(m, __shfl_xor_sync(0xffffffffu, m, off));
            float s = 0.0f;
            for (int j = lane; j <= qg; j += 32) {
                float e = __expf(row[j] - m);
                row[j] = e;
                s += e;
            }
            #pragma unroll
            for (int off = 16; off > 0; off >>= 1)
                s += __shfl_xor_sync(0xffffffffu, s, off);
            float inv = 1.0f / s;
            for (int j = lane; j < Kv; j += 32)
                row[j] = (j <= qg) ? row[j] * inv : 0.0f;
        }
    }
    __syncthreads();

    const int tc4 = tc;
    for (int vc = 0; vc < HDIM; vc += 128) {
        float o[8][4];
        #pragma unroll
        for (int i = 0; i < 8; i++)
            #pragma unroll
            for (int j = 0; j < 4; j++) o[i][j] = 0.0f;

        for (int kb = 0; kb < nkb; kb++) {
            __syncthreads();
            #pragma unroll
            for (int rep = 0; rep < 8; rep++) {
                int lin = t + rep * 256;
                int c4  = (lin & 31) << 2;
                int kk  = lin >> 5;
                *(float4*)&Vc[kk * 128 + c4] =
                    *(const float4*)(g_v + (size_t)(b * SEQ + kb * 64 + kk) * HDIM + vc + c4);
            }
            __syncthreads();

            #pragma unroll
            for (int kk4 = 0; kk4 < 64; kk4 += 4) {
                float4 a[8];
                #pragma unroll
                for (int i = 0; i < 8; i++)
                    a[i] = *(float4*)&Ps[(size_t)(tr + 8 * i) * PS_STRIDE + kb * 64 + kk4];
                #pragma unroll
                for (int u = 0; u < 4; u++) {
                    float4 bv = *(float4*)&Vc[(kk4 + u) * 128 + tc4 * 4];
                    #pragma unroll
                    for (int i = 0; i < 8; i++) {
                        float au = (u == 0) ? a[i].x : (u == 1) ? a[i].y
                                 : (u == 2) ? a[i].z : a[i].w;
                        o[i][0] += au * bv.x;
                        o[i][1] += au * bv.y;
                        o[i][2] += au * bv.z;
                        o[i][3] += au * bv.w;
                    }
                }
            }
        }

        #pragma unroll
        for (int i = 0; i < 8; i++) {
            float* dst = Out + (size_t)(b * SEQ + q0 + tr + 8 * i) * HDIM + vc + tc4 * 4;
            *(float4*)dst = make_float4(o[i][0], o[i][1], o[i][2], o[i][3]);
        }
    }
}

// ---------------------------------------------------------------------------
// Launch
// ---------------------------------------------------------------------------
extern "C" void kernel_launch(void* const* d_in, const int* in_sizes, int n_in,
                              void* d_out, int out_size)
{
    const float* x  = (const float*)d_in[0];
    const float* Wq = (const float*)d_in[1];
    const float* Wk = (const float*)d_in[2];
    const float* Wv = (const float*)d_in[3];
    float* out = (float*)d_out;

    cvt_x_kernel<<<(M_TOTAL * CDIM) / 1024, 256>>>(x);
    cvt_w_kernel<<<(3 * CDIM * HDIM) / 256, 256>>>(Wq, Wk, Wv);

    cudaFuncSetAttribute(qkv_mma_kernel, cudaFuncAttributeMaxDynamicSharedMemorySize,
                         GEMM_SMEM_BYTES);
    qkv_mma_kernel<<<dim3(9, M_TOTAL / 128), 256, GEMM_SMEM_BYTES>>>();

    const int shbytes = SMEM_FLOATS * 4;   // 99328
    cudaFuncSetAttribute(attn_kernel, cudaFuncAttributeMaxDynamicSharedMemorySize, shbytes);
    attn_kernel<<<dim3(SEQ / 64, BATCH), 256, shbytes>>>(out);
}

// round 6
// speedup vs baseline: 1.9887x; 1.2327x over previous
#include <cuda_runtime.h>
#include <cuda_bf16.h>
#include <math.h>

// Problem constants
#define BATCH 512
#define SEQ   256
#define CDIM  384
#define HDIM  384
#define M_TOTAL (BATCH * SEQ)   // 131072

// ---------------------------------------------------------------------------
// Device scratch (static: runtime allocation is forbidden)
// q/k/v stored as bf16 hi/lo pairs (error-compensated bf16 MMA operands)
// ---------------------------------------------------------------------------
__device__ __nv_bfloat16 g_qhi[(size_t)M_TOTAL * HDIM];
__device__ __nv_bfloat16 g_qlo[(size_t)M_TOTAL * HDIM];
__device__ __nv_bfloat16 g_khi[(size_t)M_TOTAL * HDIM];
__device__ __nv_bfloat16 g_klo[(size_t)M_TOTAL * HDIM];
__device__ __nv_bfloat16 g_vhi[(size_t)M_TOTAL * HDIM];
__device__ __nv_bfloat16 g_vlo[(size_t)M_TOTAL * HDIM];
// bf16 hi/lo split of X
__device__ __nv_bfloat16 g_xhi[(size_t)M_TOTAL * CDIM];
__device__ __nv_bfloat16 g_xlo[(size_t)M_TOTAL * CDIM];
// bf16 hi/lo of the three weights, TRANSPOSED to [w][n][k]
__device__ __nv_bfloat16 g_whi[(size_t)3 * HDIM * CDIM];
__device__ __nv_bfloat16 g_wlo[(size_t)3 * HDIM * CDIM];

// ---------------------------------------------------------------------------
// PTX helpers (portable to plain sm_103 target — NO tcgen05)
// ---------------------------------------------------------------------------
__device__ __forceinline__ unsigned int smem_u32(const void* p) {
    unsigned int a;
    asm("{ .reg .u64 t; cvta.to.shared.u64 t, %1; cvt.u32.u64 %0, t; }" : "=r"(a) : "l"(p));
    return a;
}
__device__ __forceinline__ void cp16(unsigned int dst, const void* src) {
    asm volatile("cp.async.cg.shared.global [%0], [%1], 16;" :: "r"(dst), "l"(src));
}
__device__ __forceinline__ void cp_commit() {
    asm volatile("cp.async.commit_group;" ::: "memory");
}
__device__ __forceinline__ void cp_wait0() {
    asm volatile("cp.async.wait_group 0;" ::: "memory");
}
__device__ __forceinline__ void ldsm_x4(unsigned int* r, unsigned int addr) {
    asm volatile("ldmatrix.sync.aligned.m8n8.x4.shared.b16 {%0,%1,%2,%3}, [%4];"
                 : "=r"(r[0]), "=r"(r[1]), "=r"(r[2]), "=r"(r[3]) : "r"(addr));
}
__device__ __forceinline__ void ldsm_x4_t(unsigned int* r, unsigned int addr) {
    asm volatile("ldmatrix.sync.aligned.m8n8.x4.trans.shared.b16 {%0,%1,%2,%3}, [%4];"
                 : "=r"(r[0]), "=r"(r[1]), "=r"(r[2]), "=r"(r[3]) : "r"(addr));
}
__device__ __forceinline__ void mma_bf16(float* c, const unsigned int* a,
                                         const unsigned int* b) {
    asm volatile("mma.sync.aligned.m16n8k16.row.col.f32.bf16.bf16.f32 "
                 "{%0,%1,%2,%3}, {%4,%5,%6,%7}, {%8,%9}, {%0,%1,%2,%3};"
                 : "+f"(c[0]), "+f"(c[1]), "+f"(c[2]), "+f"(c[3])
                 : "r"(a[0]), "r"(a[1]), "r"(a[2]), "r"(a[3]), "r"(b[0]), "r"(b[1]));
}
__device__ __forceinline__ void split_pair(float a, float b,
                                           __nv_bfloat162& h2, __nv_bfloat162& l2) {
    __nv_bfloat16 ha = __float2bfloat16(a);
    __nv_bfloat16 hb = __float2bfloat16(b);
    h2 = __halves2bfloat162(ha, hb);
    l2 = __halves2bfloat162(__float2bfloat16(a - __bfloat162float(ha)),
                            __float2bfloat16(b - __bfloat162float(hb)));
}

// ---------------------------------------------------------------------------
// Prepass 1: X fp32 -> bf16 hi/lo
// ---------------------------------------------------------------------------
__global__ __launch_bounds__(256) void cvt_x_kernel(const float* __restrict__ X)
{
    size_t i = (size_t)blockIdx.x * 256 + threadIdx.x;   // over M*C/4
    float4 v = ((const float4*)X)[i];
    __nv_bfloat162 h0, l0, h1, l1;
    split_pair(v.x, v.y, h0, l0);
    split_pair(v.z, v.w, h1, l1);
    __nv_bfloat162* dh = (__nv_bfloat162*)(g_xhi + 4 * i);
    __nv_bfloat162* dl = (__nv_bfloat162*)(g_xlo + 4 * i);
    dh[0] = h0; dh[1] = h1;
    dl[0] = l0; dl[1] = l1;
}

// ---------------------------------------------------------------------------
// Prepass 2: W fp32 [k][n] -> transposed bf16 hi/lo [w][n][k]
// ---------------------------------------------------------------------------
__global__ __launch_bounds__(256) void cvt_w_kernel(const float* __restrict__ Wq,
                                                    const float* __restrict__ Wk,
                                                    const float* __restrict__ Wv)
{
    int i = blockIdx.x * 256 + threadIdx.x;     // < 3*384*384
    int w = i / (CDIM * HDIM);
    int r = i - w * (CDIM * HDIM);
    int k = r / HDIM;
    int n = r - k * HDIM;
    const float* W = (w == 0) ? Wq : ((w == 1) ? Wk : Wv);
    float v = W[(size_t)k * HDIM + n];
    __nv_bfloat16 h = __float2bfloat16(v);
    size_t o = ((size_t)w * HDIM + n) * CDIM + k;
    g_whi[o] = h;
    g_wlo[o] = __float2bfloat16(v - __bfloat162float(h));
}

// ---------------------------------------------------------------------------
// Kernel: QKV GEMM via mma.sync. CTA 128x128, K chunks 64, double-buffered.
// D = Ahi*Bhi + Ahi*Blo + Alo*Bhi; epilogue re-splits fp32 acc -> bf16 hi/lo.
// ---------------------------------------------------------------------------
#define ROWB   144            // padded row stride in bytes (72 bf16)
#define TILE_B (128 * ROWB)   // 18432 bytes per operand tile
#define STG_B  (4 * TILE_B)   // 73728 bytes per stage
#define GEMM_SMEM_BYTES (2 * STG_B)   // 147456
#define NCHUNK 6

__global__ __launch_bounds__(256, 1) void qkv_mma_kernel()
{
    extern __shared__ char smem[];
    const unsigned int sb = smem_u32(smem);
    const int t    = threadIdx.x;
    const int wid  = t >> 5;
    const int lane = t & 31;

    const int nblk = blockIdx.x;           // 0..8
    const int w    = nblk / 3;             // weight select
    const int n0   = (nblk - w * 3) * 128; // col offset within weight
    const int m0   = blockIdx.y * 128;

    const __nv_bfloat16* whi = g_whi + (size_t)w * HDIM * CDIM;
    const __nv_bfloat16* wlo = g_wlo + (size_t)w * HDIM * CDIM;

    const int wm = (wid & 3) * 32;
    const int wn = (wid >> 2) * 64;

    const unsigned int a_lane = (unsigned)((lane & 15) * ROWB + (lane >> 4) * 16);
    const unsigned int b_lane = (unsigned)(((lane & 7) + ((lane >> 4) << 3)) * ROWB
                                           + ((lane >> 3) & 1) * 16);

    float acc[2][8][4];
    #pragma unroll
    for (int mt = 0; mt < 2; mt++)
        #pragma unroll
        for (int nt = 0; nt < 8; nt++)
            #pragma unroll
            for (int q = 0; q < 4; q++) acc[mt][nt][q] = 0.0f;

    auto load_chunk = [&](int c, int stage) {
        const unsigned int s0 = sb + stage * STG_B;
        #pragma unroll
        for (int it = 0; it < 4; it++) {
            int s = t + it * 256;
            int r = s >> 3, j = s & 7;
            unsigned int d = (unsigned)(r * ROWB + j * 16);
            const __nv_bfloat16* sh = g_xhi + (size_t)(m0 + r) * CDIM + c * 64 + j * 8;
            const __nv_bfloat16* sl = g_xlo + (size_t)(m0 + r) * CDIM + c * 64 + j * 8;
            cp16(s0 + d, sh);
            cp16(s0 + TILE_B + d, sl);
        }
        #pragma unroll
        for (int it = 0; it < 4; it++) {
            int s = t + it * 256;
            int r = s >> 3, j = s & 7;
            unsigned int d = (unsigned)(r * ROWB + j * 16);
            const __nv_bfloat16* sh = whi + (size_t)(n0 + r) * CDIM + c * 64 + j * 8;
            const __nv_bfloat16* sl = wlo + (size_t)(n0 + r) * CDIM + c * 64 + j * 8;
            cp16(s0 + 2 * TILE_B + d, sh);
            cp16(s0 + 3 * TILE_B + d, sl);
        }
        cp_commit();
    };

    load_chunk(0, 0);

    for (int c = 0; c < NCHUNK; c++) {
        const int stage = c & 1;
        if (c + 1 < NCHUNK) load_chunk(c + 1, stage ^ 1);

        if (c + 1 < NCHUNK)
            asm volatile("cp.async.wait_group 1;" ::: "memory");
        else
            cp_wait0();
        __syncthreads();

        const unsigned int sa_hi = sb + stage * STG_B;
        const unsigned int sa_lo = sa_hi + TILE_B;
        const unsigned int sb_hi = sa_hi + 2 * TILE_B;
        const unsigned int sb_lo = sa_hi + 3 * TILE_B;

        #pragma unroll
        for (int kk = 0; kk < 4; kk++) {
            const unsigned int koff = kk * 32;
            unsigned int Ahi[2][4], Alo[2][4];
            #pragma unroll
            for (int mt = 0; mt < 2; mt++) {
                unsigned int ab = (unsigned)((wm + mt * 16) * ROWB) + koff + a_lane;
                ldsm_x4(Ahi[mt], sa_hi + ab);
                ldsm_x4(Alo[mt], sa_lo + ab);
            }
            #pragma unroll
            for (int nt2 = 0; nt2 < 4; nt2++) {
                unsigned int bb = (unsigned)((wn + nt2 * 16) * ROWB) + koff + b_lane;
                unsigned int Bhi[4], Blo[4];
                ldsm_x4(Bhi, sb_hi + bb);
                ldsm_x4(Blo, sb_lo + bb);
                #pragma unroll
                for (int mt = 0; mt < 2; mt++) {
                    mma_bf16(acc[mt][nt2 * 2 + 0], Ahi[mt], Bhi + 0);
                    mma_bf16(acc[mt][nt2 * 2 + 1], Ahi[mt], Bhi + 2);
                    mma_bf16(acc[mt][nt2 * 2 + 0], Ahi[mt], Blo + 0);
                    mma_bf16(acc[mt][nt2 * 2 + 1], Ahi[mt], Blo + 2);
                    mma_bf16(acc[mt][nt2 * 2 + 0], Alo[mt], Bhi + 0);
                    mma_bf16(acc[mt][nt2 * 2 + 1], Alo[mt], Bhi + 2);
                }
            }
        }
        __syncthreads();
    }

    // Epilogue: split fp32 acc -> bf16 hi/lo pairs, write to q/k/v arrays
    __nv_bfloat16* ohi = (w == 0) ? g_qhi : ((w == 1) ? g_khi : g_vhi);
    __nv_bfloat16* olo = (w == 0) ? g_qlo : ((w == 1) ? g_klo : g_vlo);
    #pragma unroll
    for (int mt = 0; mt < 2; mt++) {
        int r0 = m0 + wm + mt * 16 + (lane >> 2);
        #pragma unroll
        for (int nt = 0; nt < 8; nt++) {
            int cc = n0 + wn + nt * 8 + 2 * (lane & 3);
            __nv_bfloat162 h2, l2;
            split_pair(acc[mt][nt][0], acc[mt][nt][1], h2, l2);
            *(__nv_bfloat162*)(ohi + (size_t)r0 * HDIM + cc) = h2;
            *(__nv_bfloat162*)(olo + (size_t)r0 * HDIM + cc) = l2;
            split_pair(acc[mt][nt][2], acc[mt][nt][3], h2, l2);
            *(__nv_bfloat162*)(ohi + (size_t)(r0 + 8) * HDIM + cc) = h2;
            *(__nv_bfloat162*)(olo + (size_t)(r0 + 8) * HDIM + cc) = l2;
        }
    }
}

// ---------------------------------------------------------------------------
// Kernel: causal attention via mma.sync, hi/lo compensated on both GEMMs.
// One CTA = (batch, 64-query tile). 8 warps.
// Phase A: S[64,256] = Q K^T over 6 h-chunks of 64 (warps 2m x 4n)
// Phase B: softmax in smem fp32 (exact), then P -> bf16 hi/lo
// Phase C: O = P V over 6 h-chunks of 64 (V fragments via ldmatrix.trans)
// ---------------------------------------------------------------------------
// smem byte offsets
#define AT_SQH 0u
#define AT_SQL 9216u
#define AT_SKH 18432u
#define AT_SKL 55296u
#define AT_PS  0u          // fp32 [64][260], overlays phase A after it ends
#define AT_PHI 66560u      // bf16 [64][264]
#define AT_PLO 100352u
#define AT_SVH 134144u     // bf16 [256 rows][72], ROWB=144
#define AT_SVL 171008u
#define AT_SMEM_BYTES 207872

__global__ __launch_bounds__(256, 1) void attn_mma_kernel(float* __restrict__ Out)
{
    extern __shared__ char smem[];
    const unsigned int sb = smem_u32(smem);
    const int t    = threadIdx.x;
    const int wid  = t >> 5;
    const int lane = t & 31;
    const int bq   = blockIdx.x;          // 0..3
    const int b    = blockIdx.y;          // 0..511
    const int q0   = bq * 64;
    const int Kv   = (bq + 1) * 64;       // valid keys
    const float scl = rsqrtf((float)HDIM);

    const int wm = (wid & 1) * 32;        // warp m offset (2 m-warps)
    const int wn = (wid >> 1) * 64;       // warp n offset, phase A (4 n-warps)

    const unsigned int a_lane  = (unsigned)((lane & 15) * ROWB + (lane >> 4) * 16);
    const unsigned int b_lane  = (unsigned)(((lane & 7) + ((lane >> 4) << 3)) * ROWB
                                            + ((lane >> 3) & 1) * 16);
    const unsigned int p_lane  = (unsigned)((lane & 15) * 528 + (lane >> 4) * 16);
    const unsigned int v_lane  = (unsigned)((lane & 15) * ROWB + (lane >> 4) * 16);

    // ---------------- Phase A: S = Q K^T -----------------------------------
    float sacc[2][8][4];
    #pragma unroll
    for (int mt = 0; mt < 2; mt++)
        #pragma unroll
        for (int nt = 0; nt < 8; nt++)
            #pragma unroll
            for (int q = 0; q < 4; q++) sacc[mt][nt][q] = 0.0f;

    const bool sact = (wn < Kv);

    for (int hc = 0; hc < 6; hc++) {
        // Q chunk: 64 rows x 64 cols (hi/lo)
        #pragma unroll
        for (int it = 0; it < 2; it++) {
            int s = t + it * 256;
            int r = s >> 3, j = s & 7;
            unsigned int d = (unsigned)(r * ROWB + j * 16);
            size_t go = (size_t)(b * SEQ + q0 + r) * HDIM + hc * 64 + j * 8;
            cp16(sb + AT_SQH + d, g_qhi + go);
            cp16(sb + AT_SQL + d, g_qlo + go);
        }
        // K chunk: Kv rows x 64 cols (hi/lo)
        #pragma unroll
        for (int it = 0; it < 8; it++) {
            int s = t + it * 256;
            int r = s >> 3, j = s & 7;
            if (r < Kv) {
                unsigned int d = (unsigned)(r * ROWB + j * 16);
                size_t go = (size_t)(b * SEQ + r) * HDIM + hc * 64 + j * 8;
                cp16(sb + AT_SKH + d, g_khi + go);
                cp16(sb + AT_SKL + d, g_klo + go);
            }
        }
        cp_commit();
        cp_wait0();
        __syncthreads();

        if (sact) {
            #pragma unroll
            for (int kk = 0; kk < 4; kk++) {
                const unsigned int koff = kk * 32;
                unsigned int Ahi[2][4], Alo[2][4];
                #pragma unroll
                for (int mt = 0; mt < 2; mt++) {
                    unsigned int ab = (unsigned)((wm + mt * 16) * ROWB) + koff + a_lane;
                    ldsm_x4(Ahi[mt], sb + AT_SQH + ab);
                    ldsm_x4(Alo[mt], sb + AT_SQL + ab);
                }
                #pragma unroll
                for (int nt2 = 0; nt2 < 4; nt2++) {
                    unsigned int bb = (unsigned)((wn + nt2 * 16) * ROWB) + koff + b_lane;
                    unsigned int Bhi[4], Blo[4];
                    ldsm_x4(Bhi, sb + AT_SKH + bb);
                    ldsm_x4(Blo, sb + AT_SKL + bb);
                    #pragma unroll
                    for (int mt = 0; mt < 2; mt++) {
                        mma_bf16(sacc[mt][nt2 * 2 + 0], Ahi[mt], Bhi + 0);
                        mma_bf16(sacc[mt][nt2 * 2 + 1], Ahi[mt], Bhi + 2);
                        mma_bf16(sacc[mt][nt2 * 2 + 0], Ahi[mt], Blo + 0);
                        mma_bf16(sacc[mt][nt2 * 2 + 1], Ahi[mt], Blo + 2);
                        mma_bf16(sacc[mt][nt2 * 2 + 0], Alo[mt], Bhi + 0);
                        mma_bf16(sacc[mt][nt2 * 2 + 1], Alo[mt], Bhi + 2);
                    }
                }
            }
        }
        __syncthreads();
    }

    // ---------------- Phase B: scatter S, softmax, split P -----------------
    float* Ps = (float*)(smem + AT_PS);
    #pragma unroll
    for (int mt = 0; mt < 2; mt++) {
        int r = wm + mt * 16 + (lane >> 2);
        #pragma unroll
        for (int nt = 0; nt < 8; nt++) {
            int cc = wn + nt * 8 + 2 * (lane & 3);
            *(float2*)&Ps[r * 260 + cc] =
                make_float2(sacc[mt][nt][0] * scl, sacc[mt][nt][1] * scl);
            *(float2*)&Ps[(r + 8) * 260 + cc] =
                make_float2(sacc[mt][nt][2] * scl, sacc[mt][nt][3] * scl);
        }
    }
    __syncthreads();

    {
        const int wq = wid;                 // warp handles rows wq*8 .. wq*8+7
        for (int rr = 0; rr < 8; rr++) {
            int r  = wq * 8 + rr;
            int qg = q0 + r;                // valid keys: 0..qg
            float* row = Ps + (size_t)r * 260;
            float m = -1e30f;
            for (int j = lane; j <= qg; j += 32) m = fmaxf(m, row[j]);
            #pragma unroll
            for (int off = 16; off > 0; off >>= 1)
                m = fmaxf(m, __shfl_xor_sync(0xffffffffu, m, off));
            float s = 0.0f;
            for (int j = lane; j <= qg; j += 32) {
                float e = __expf(row[j] - m);
                row[j] = e;
                s += e;
            }
            #pragma unroll
            for (int off = 16; off > 0; off >>= 1)
                s += __shfl_xor_sync(0xffffffffu, s, off);
            float inv = 1.0f / s;
            for (int j = lane; j < Kv; j += 32)
                row[j] = (j <= qg) ? row[j] * inv : 0.0f;
        }
    }
    __syncthreads();

    // P -> bf16 hi/lo (rows 64, cols 256; cols >= Kv are zero, harmless)
    {
        __nv_bfloat16* Ph = (__nv_bfloat16*)(smem + AT_PHI);
        __nv_bfloat16* Pl = (__nv_bfloat16*)(smem + AT_PLO);
        for (int i = t; i < 64 * 256; i += 256) {
            int r = i >> 8, c = i & 255;
            float p = Ps[r * 260 + c];
            __nv_bfloat16 h = __float2bfloat16(p);
            Ph[r * 264 + c] = h;
            Pl[r * 264 + c] = __float2bfloat16(p - __bfloat162float(h));
        }
    }
    __syncthreads();

    // ---------------- Phase C: O = P V -------------------------------------
    const int wnc = (wid >> 1) * 16;        // warp n offset within 64-col chunk
    const int nks = Kv >> 4;                // k16 steps over keys

    for (int hc = 0; hc < 6; hc++) {
        // V chunk: Kv rows x 64 cols (hi/lo)
        #pragma unroll
        for (int it = 0; it < 8; it++) {
            int s = t + it * 256;
            int r = s >> 3, j = s & 7;
            if (r < Kv) {
                unsigned int d = (unsigned)(r * ROWB + j * 16);
                size_t go = (size_t)(b * SEQ + r) * HDIM + hc * 64 + j * 8;
                cp16(sb + AT_SVH + d, g_vhi + go);
                cp16(sb + AT_SVL + d, g_vlo + go);
            }
        }
        cp_commit();
        cp_wait0();
        __syncthreads();

        float oacc[2][2][4];
        #pragma unroll
        for (int mt = 0; mt < 2; mt++)
            #pragma unroll
            for (int nt = 0; nt < 2; nt++)
                #pragma unroll
                for (int q = 0; q < 4; q++) oacc[mt][nt][q] = 0.0f;

        for (int ks = 0; ks < nks; ks++) {
            unsigned int Phf[2][4], Plf[2][4];
            #pragma unroll
            for (int mt = 0; mt < 2; mt++) {
                unsigned int pa = (unsigned)((wm + mt * 16) * 528) + ks * 32 + p_lane;
                ldsm_x4(Phf[mt], sb + AT_PHI + pa);
                ldsm_x4(Plf[mt], sb + AT_PLO + pa);
            }
            unsigned int Vh[4], Vl[4];
            unsigned int va = (unsigned)(ks * 16 * ROWB) + (unsigned)(wnc * 2) + v_lane;
            ldsm_x4_t(Vh, sb + AT_SVH + va);
            ldsm_x4_t(Vl, sb + AT_SVL + va);
            #pragma unroll
            for (int mt = 0; mt < 2; mt++) {
                #pragma unroll
                for (int nt = 0; nt < 2; nt++) {
                    mma_bf16(oacc[mt][nt], Phf[mt], Vh + nt * 2);
                    mma_bf16(oacc[mt][nt], Phf[mt], Vl + nt * 2);
                    mma_bf16(oacc[mt][nt], Plf[mt], Vh + nt * 2);
                }
            }
        }

        // write O chunk
        #pragma unroll
        for (int mt = 0; mt < 2; mt++) {
            int gr = b * SEQ + q0 + wm + mt * 16 + (lane >> 2);
            #pragma unroll
            for (int nt = 0; nt < 2; nt++) {
                int gc = hc * 64 + wnc + nt * 8 + 2 * (lane & 3);
                *(float2*)(Out + (size_t)gr * HDIM + gc) =
                    make_float2(oacc[mt][nt][0], oacc[mt][nt][1]);
                *(float2*)(Out + (size_t)(gr + 8) * HDIM + gc) =
                    make_float2(oacc[mt][nt][2], oacc[mt][nt][3]);
            }
        }
        __syncthreads();
    }
}

// ---------------------------------------------------------------------------
// Launch
// ---------------------------------------------------------------------------
extern "C" void kernel_launch(void* const* d_in, const int* in_sizes, int n_in,
                              void* d_out, int out_size)
{
    const float* x  = (const float*)d_in[0];
    const float* Wq = (const float*)d_in[1];
    const float* Wk = (const float*)d_in[2];
    const float* Wv = (const float*)d_in[3];
    float* out = (float*)d_out;

    cvt_x_kernel<<<(M_TOTAL * CDIM) / 1024, 256>>>(x);
    cvt_w_kernel<<<(3 * CDIM * HDIM) / 256, 256>>>(Wq, Wk, Wv);

    cudaFuncSetAttribute(qkv_mma_kernel, cudaFuncAttributeMaxDynamicSharedMemorySize,
                         GEMM_SMEM_BYTES);
    qkv_mma_kernel<<<dim3(9, M_TOTAL / 128), 256, GEMM_SMEM_BYTES>>>();

    cudaFuncSetAttribute(attn_mma_kernel, cudaFuncAttributeMaxDynamicSharedMemorySize,
                         AT_SMEM_BYTES);
    attn_mma_kernel<<<dim3(SEQ / 64, BATCH), 256, AT_SMEM_BYTES>>>(out);
}

// round 7
// speedup vs baseline: 2.2602x; 1.1365x over previous
#include <cuda_runtime.h>
#include <cuda_bf16.h>
#include <math.h>

// Problem constants
#define BATCH 512
#define SEQ   256
#define CDIM  384
#define HDIM  384
#define M_TOTAL (BATCH * SEQ)   // 131072

// ---------------------------------------------------------------------------
// Device scratch (static: runtime allocation is forbidden)
// q/k/v stored as bf16 hi/lo pairs (error-compensated bf16 MMA operands)
// ---------------------------------------------------------------------------
__device__ __nv_bfloat16 g_qhi[(size_t)M_TOTAL * HDIM];
__device__ __nv_bfloat16 g_qlo[(size_t)M_TOTAL * HDIM];
__device__ __nv_bfloat16 g_khi[(size_t)M_TOTAL * HDIM];
__device__ __nv_bfloat16 g_klo[(size_t)M_TOTAL * HDIM];
__device__ __nv_bfloat16 g_vhi[(size_t)M_TOTAL * HDIM];
__device__ __nv_bfloat16 g_vlo[(size_t)M_TOTAL * HDIM];
// bf16 hi/lo split of X
__device__ __nv_bfloat16 g_xhi[(size_t)M_TOTAL * CDIM];
__device__ __nv_bfloat16 g_xlo[(size_t)M_TOTAL * CDIM];
// bf16 hi/lo of the three weights, TRANSPOSED to [w][n][k]
__device__ __nv_bfloat16 g_whi[(size_t)3 * HDIM * CDIM];
__device__ __nv_bfloat16 g_wlo[(size_t)3 * HDIM * CDIM];

// ---------------------------------------------------------------------------
// PTX helpers (portable to plain sm_103 target — NO tcgen05)
// ---------------------------------------------------------------------------
__device__ __forceinline__ unsigned int smem_u32(const void* p) {
    unsigned int a;
    asm("{ .reg .u64 t; cvta.to.shared.u64 t, %1; cvt.u32.u64 %0, t; }" : "=r"(a) : "l"(p));
    return a;
}
__device__ __forceinline__ void cp16(unsigned int dst, const void* src) {
    asm volatile("cp.async.cg.shared.global [%0], [%1], 16;" :: "r"(dst), "l"(src));
}
__device__ __forceinline__ void cp_commit() {
    asm volatile("cp.async.commit_group;" ::: "memory");
}
__device__ __forceinline__ void cp_wait0() {
    asm volatile("cp.async.wait_group 0;" ::: "memory");
}
__device__ __forceinline__ void cp_wait1() {
    asm volatile("cp.async.wait_group 1;" ::: "memory");
}
__device__ __forceinline__ void ldsm_x4(unsigned int* r, unsigned int addr) {
    asm volatile("ldmatrix.sync.aligned.m8n8.x4.shared.b16 {%0,%1,%2,%3}, [%4];"
                 : "=r"(r[0]), "=r"(r[1]), "=r"(r[2]), "=r"(r[3]) : "r"(addr));
}
__device__ __forceinline__ void ldsm_x4_t(unsigned int* r, unsigned int addr) {
    asm volatile("ldmatrix.sync.aligned.m8n8.x4.trans.shared.b16 {%0,%1,%2,%3}, [%4];"
                 : "=r"(r[0]), "=r"(r[1]), "=r"(r[2]), "=r"(r[3]) : "r"(addr));
}
__device__ __forceinline__ void mma_bf16(float* c, const unsigned int* a,
                                         const unsigned int* b) {
    asm volatile("mma.sync.aligned.m16n8k16.row.col.f32.bf16.bf16.f32 "
                 "{%0,%1,%2,%3}, {%4,%5,%6,%7}, {%8,%9}, {%0,%1,%2,%3};"
                 : "+f"(c[0]), "+f"(c[1]), "+f"(c[2]), "+f"(c[3])
                 : "r"(a[0]), "r"(a[1]), "r"(a[2]), "r"(a[3]), "r"(b[0]), "r"(b[1]));
}
__device__ __forceinline__ void split_pair(float a, float b,
                                           __nv_bfloat162& h2, __nv_bfloat162& l2) {
    __nv_bfloat16 ha = __float2bfloat16(a);
    __nv_bfloat16 hb = __float2bfloat16(b);
    h2 = __halves2bfloat162(ha, hb);
    l2 = __halves2bfloat162(__float2bfloat16(a - __bfloat162float(ha)),
                            __float2bfloat16(b - __bfloat162float(hb)));
}

// ---------------------------------------------------------------------------
// Prepass 1: X fp32 -> bf16 hi/lo
// ---------------------------------------------------------------------------
__global__ __launch_bounds__(256) void cvt_x_kernel(const float* __restrict__ X)
{
    size_t i = (size_t)blockIdx.x * 256 + threadIdx.x;   // over M*C/4
    float4 v = ((const float4*)X)[i];
    __nv_bfloat162 h0, l0, h1, l1;
    split_pair(v.x, v.y, h0, l0);
    split_pair(v.z, v.w, h1, l1);
    __nv_bfloat162* dh = (__nv_bfloat162*)(g_xhi + 4 * i);
    __nv_bfloat162* dl = (__nv_bfloat162*)(g_xlo + 4 * i);
    dh[0] = h0; dh[1] = h1;
    dl[0] = l0; dl[1] = l1;
}

// ---------------------------------------------------------------------------
// Prepass 2: W fp32 [k][n] -> transposed bf16 hi/lo [w][n][k]
// ---------------------------------------------------------------------------
__global__ __launch_bounds__(256) void cvt_w_kernel(const float* __restrict__ Wq,
                                                    const float* __restrict__ Wk,
                                                    const float* __restrict__ Wv)
{
    int i = blockIdx.x * 256 + threadIdx.x;     // < 3*384*384
    int w = i / (CDIM * HDIM);
    int r = i - w * (CDIM * HDIM);
    int k = r / HDIM;
    int n = r - k * HDIM;
    const float* W = (w == 0) ? Wq : ((w == 1) ? Wk : Wv);
    float v = W[(size_t)k * HDIM + n];
    __nv_bfloat16 h = __float2bfloat16(v);
    size_t o = ((size_t)w * HDIM + n) * CDIM + k;
    g_whi[o] = h;
    g_wlo[o] = __float2bfloat16(v - __bfloat162float(h));
}

// ---------------------------------------------------------------------------
// Kernel: QKV GEMM via mma.sync. CTA 128x128, K chunks of 32, double-buffered,
// 2 CTAs/SM. D = Ahi*Bhi + Ahi*Blo + Alo*Bhi; epilogue splits -> bf16 hi/lo.
// ---------------------------------------------------------------------------
#define ROWB2  80             // padded row stride (32 bf16 = 64B data + 16 pad)
#define TILE2  (128 * ROWB2)  // 10240 bytes per operand tile
#define STG2   (4 * TILE2)    // 40960 bytes per stage
#define QKV_SMEM_BYTES (2 * STG2)   // 81920 -> 2 CTAs/SM
#define NCH2   12

__global__ __launch_bounds__(256, 2) void qkv_mma_kernel()
{
    extern __shared__ char smem[];
    const unsigned int sb = smem_u32(smem);
    const int t    = threadIdx.x;
    const int wid  = t >> 5;
    const int lane = t & 31;

    const int nblk = blockIdx.x;           // 0..8
    const int w    = nblk / 3;             // weight select
    const int n0   = (nblk - w * 3) * 128; // col offset within weight
    const int m0   = blockIdx.y * 128;

    const __nv_bfloat16* whi = g_whi + (size_t)w * HDIM * CDIM;
    const __nv_bfloat16* wlo = g_wlo + (size_t)w * HDIM * CDIM;

    const int wm = (wid & 3) * 32;
    const int wn = (wid >> 2) * 64;

    const unsigned int a_lane = (unsigned)((lane & 15) * ROWB2 + (lane >> 4) * 16);
    const unsigned int b_lane = (unsigned)(((lane & 7) + ((lane >> 4) << 3)) * ROWB2
                                           + ((lane >> 3) & 1) * 16);

    float acc[2][8][4];
    #pragma unroll
    for (int mt = 0; mt < 2; mt++)
        #pragma unroll
        for (int nt = 0; nt < 8; nt++)
            #pragma unroll
            for (int q = 0; q < 4; q++) acc[mt][nt][q] = 0.0f;

    auto load_chunk = [&](int c, int stage) {
        const unsigned int s0 = sb + stage * STG2;
        #pragma unroll
        for (int it = 0; it < 2; it++) {
            int s = t + it * 256;
            int r = s >> 2, j = s & 3;
            unsigned int d = (unsigned)(r * ROWB2 + j * 16);
            size_t ao = (size_t)(m0 + r) * CDIM + c * 32 + j * 8;
            size_t bo = (size_t)(n0 + r) * CDIM + c * 32 + j * 8;
            cp16(s0 + d,             g_xhi + ao);
            cp16(s0 + TILE2 + d,     g_xlo + ao);
            cp16(s0 + 2 * TILE2 + d, whi + bo);
            cp16(s0 + 3 * TILE2 + d, wlo + bo);
        }
        cp_commit();
    };

    load_chunk(0, 0);

    for (int c = 0; c < NCH2; c++) {
        const int stage = c & 1;
        if (c + 1 < NCH2) load_chunk(c + 1, stage ^ 1);

        if (c + 1 < NCH2) cp_wait1(); else cp_wait0();
        __syncthreads();

        const unsigned int sa_hi = sb + stage * STG2;
        const unsigned int sa_lo = sa_hi + TILE2;
        const unsigned int sb_hi = sa_hi + 2 * TILE2;
        const unsigned int sb_lo = sa_hi + 3 * TILE2;

        #pragma unroll
        for (int kk = 0; kk < 2; kk++) {
            const unsigned int koff = kk * 32;
            unsigned int Ahi[2][4], Alo[2][4];
            #pragma unroll
            for (int mt = 0; mt < 2; mt++) {
                unsigned int ab = (unsigned)((wm + mt * 16) * ROWB2) + koff + a_lane;
                ldsm_x4(Ahi[mt], sa_hi + ab);
                ldsm_x4(Alo[mt], sa_lo + ab);
            }
            #pragma unroll
            for (int nt2 = 0; nt2 < 4; nt2++) {
                unsigned int bb = (unsigned)((wn + nt2 * 16) * ROWB2) + koff + b_lane;
                unsigned int Bhi[4], Blo[4];
                ldsm_x4(Bhi, sb_hi + bb);
                ldsm_x4(Blo, sb_lo + bb);
                #pragma unroll
                for (int mt = 0; mt < 2; mt++) {
                    mma_bf16(acc[mt][nt2 * 2 + 0], Ahi[mt], Bhi + 0);
                    mma_bf16(acc[mt][nt2 * 2 + 1], Ahi[mt], Bhi + 2);
                    mma_bf16(acc[mt][nt2 * 2 + 0], Ahi[mt], Blo + 0);
                    mma_bf16(acc[mt][nt2 * 2 + 1], Ahi[mt], Blo + 2);
                    mma_bf16(acc[mt][nt2 * 2 + 0], Alo[mt], Bhi + 0);
                    mma_bf16(acc[mt][nt2 * 2 + 1], Alo[mt], Bhi + 2);
                }
            }
        }
        __syncthreads();
    }

    // Epilogue: split fp32 acc -> bf16 hi/lo pairs, write to q/k/v arrays
    __nv_bfloat16* ohi = (w == 0) ? g_qhi : ((w == 1) ? g_khi : g_vhi);
    __nv_bfloat16* olo = (w == 0) ? g_qlo : ((w == 1) ? g_klo : g_vlo);
    #pragma unroll
    for (int mt = 0; mt < 2; mt++) {
        int r0 = m0 + wm + mt * 16 + (lane >> 2);
        #pragma unroll
        for (int nt = 0; nt < 8; nt++) {
            int cc = n0 + wn + nt * 8 + 2 * (lane & 3);
            __nv_bfloat162 h2, l2;
            split_pair(acc[mt][nt][0], acc[mt][nt][1], h2, l2);
            *(__nv_bfloat162*)(ohi + (size_t)r0 * HDIM + cc) = h2;
            *(__nv_bfloat162*)(olo + (size_t)r0 * HDIM + cc) = l2;
            split_pair(acc[mt][nt][2], acc[mt][nt][3], h2, l2);
            *(__nv_bfloat162*)(ohi + (size_t)(r0 + 8) * HDIM + cc) = h2;
            *(__nv_bfloat162*)(olo + (size_t)(r0 + 8) * HDIM + cc) = l2;
        }
    }
}

// ---------------------------------------------------------------------------
// Kernel: causal attention via mma.sync, hi/lo compensated, double-buffered
// streaming of Q/K (phase A) and V (phase C).
// Smem overlay plan (bytes):
//   P_HI [0,33792) P_LO [33792,67584)     (phase B/C)
//   QB0 [0,18432) QB1 [18432,36864)       (phase A; hi at +0, lo at +9216)
//   KB0 [36864,110592) KB1 [110592,184320)(phase A; hi at +0, lo at +36864)
//   Ps  [67584,134144) fp32 64x260        (between phase A end and P split)
//   VB0 [67584,141312) VB1 [141312,215040)(phase C; hi at +0, lo at +36864)
// ---------------------------------------------------------------------------
#define ROWB 144
#define AT2_PHI  0u
#define AT2_PLO  33792u
#define AT2_QB0  0u
#define AT2_QB1  18432u
#define AT2_KB0  36864u
#define AT2_KB1  110592u
#define AT2_PS   67584u
#define AT2_VB0  67584u
#define AT2_VB1  141312u
#define AT2_SMEM_BYTES 215040

__global__ __launch_bounds__(256, 1) void attn_mma_kernel(float* __restrict__ Out)
{
    extern __shared__ char smem[];
    const unsigned int sb = smem_u32(smem);
    const int t    = threadIdx.x;
    const int wid  = t >> 5;
    const int lane = t & 31;
    const int bq   = blockIdx.x;          // 0..3
    const int b    = blockIdx.y;          // 0..511
    const int q0   = bq * 64;
    const int Kv   = (bq + 1) * 64;       // valid keys
    const float scl = rsqrtf((float)HDIM);

    const int wm = (wid & 1) * 32;        // warp m offset (2 m-warps)
    const int wn = (wid >> 1) * 64;       // warp n offset, phase A (4 n-warps)

    const unsigned int a_lane = (unsigned)((lane & 15) * ROWB + (lane >> 4) * 16);
    const unsigned int b_lane = (unsigned)(((lane & 7) + ((lane >> 4) << 3)) * ROWB
                                           + ((lane >> 3) & 1) * 16);
    const unsigned int p_lane = (unsigned)((lane & 15) * 528 + (lane >> 4) * 16);
    const unsigned int v_lane = (unsigned)((lane & 15) * ROWB + (lane >> 4) * 16);

    // ---------------- Phase A: S = Q K^T (double-buffered chunks) ----------
    float sacc[2][8][4];
    #pragma unroll
    for (int mt = 0; mt < 2; mt++)
        #pragma unroll
        for (int nt = 0; nt < 8; nt++)
            #pragma unroll
            for (int q = 0; q < 4; q++) sacc[mt][nt][q] = 0.0f;

    const bool sact = (wn < Kv);

    auto load_qk = [&](int hc, int buf) {
        const unsigned int qb = sb + (buf ? AT2_QB1 : AT2_QB0);
        const unsigned int kb = sb + (buf ? AT2_KB1 : AT2_KB0);
        #pragma unroll
        for (int it = 0; it < 2; it++) {
            int s = t + it * 256;
            int r = s >> 3, j = s & 7;
            unsigned int d = (unsigned)(r * ROWB + j * 16);
            size_t go = (size_t)(b * SEQ + q0 + r) * HDIM + hc * 64 + j * 8;
            cp16(qb + d, g_qhi + go);
            cp16(qb + 9216u + d, g_qlo + go);
        }
        #pragma unroll
        for (int it = 0; it < 8; it++) {
            int s = t + it * 256;
            int r = s >> 3, j = s & 7;
            if (r < Kv) {
                unsigned int d = (unsigned)(r * ROWB + j * 16);
                size_t go = (size_t)(b * SEQ + r) * HDIM + hc * 64 + j * 8;
                cp16(kb + d, g_khi + go);
                cp16(kb + 36864u + d, g_klo + go);
            }
        }
        cp_commit();
    };

    load_qk(0, 0);

    for (int hc = 0; hc < 6; hc++) {
        const int buf = hc & 1;
        if (hc + 1 < 6) load_qk(hc + 1, buf ^ 1);
        if (hc + 1 < 6) cp_wait1(); else cp_wait0();
        __syncthreads();

        if (sact) {
            const unsigned int sqh = sb + (buf ? AT2_QB1 : AT2_QB0);
            const unsigned int sql = sqh + 9216u;
            const unsigned int skh = sb + (buf ? AT2_KB1 : AT2_KB0);
            const unsigned int skl = skh + 36864u;
            #pragma unroll
            for (int kk = 0; kk < 4; kk++) {
                const unsigned int koff = kk * 32;
                unsigned int Ahi[2][4], Alo[2][4];
                #pragma unroll
                for (int mt = 0; mt < 2; mt++) {
                    unsigned int ab = (unsigned)((wm + mt * 16) * ROWB) + koff + a_lane;
                    ldsm_x4(Ahi[mt], sqh + ab);
                    ldsm_x4(Alo[mt], sql + ab);
                }
                #pragma unroll
                for (int nt2 = 0; nt2 < 4; nt2++) {
                    unsigned int bb = (unsigned)((wn + nt2 * 16) * ROWB) + koff + b_lane;
                    unsigned int Bhi[4], Blo[4];
                    ldsm_x4(Bhi, skh + bb);
                    ldsm_x4(Blo, skl + bb);
                    #pragma unroll
                    for (int mt = 0; mt < 2; mt++) {
                        mma_bf16(sacc[mt][nt2 * 2 + 0], Ahi[mt], Bhi + 0);
                        mma_bf16(sacc[mt][nt2 * 2 + 1], Ahi[mt], Bhi + 2);
                        mma_bf16(sacc[mt][nt2 * 2 + 0], Ahi[mt], Blo + 0);
                        mma_bf16(sacc[mt][nt2 * 2 + 1], Ahi[mt], Blo + 2);
                        mma_bf16(sacc[mt][nt2 * 2 + 0], Alo[mt], Bhi + 0);
                        mma_bf16(sacc[mt][nt2 * 2 + 1], Alo[mt], Bhi + 2);
                    }
                }
            }
        }
        __syncthreads();
    }

    // ---------------- Phase B: scatter S, softmax, split P -----------------
    float* Ps = (float*)(smem + AT2_PS);
    #pragma unroll
    for (int mt = 0; mt < 2; mt++) {
        int r = wm + mt * 16 + (lane >> 2);
        #pragma unroll
        for (int nt = 0; nt < 8; nt++) {
            int cc = wn + nt * 8 + 2 * (lane & 3);
            *(float2*)&Ps[r * 260 + cc] =
                make_float2(sacc[mt][nt][0] * scl, sacc[mt][nt][1] * scl);
            *(float2*)&Ps[(r + 8) * 260 + cc] =
                make_float2(sacc[mt][nt][2] * scl, sacc[mt][nt][3] * scl);
        }
    }
    __syncthreads();

    {
        const int wq = wid;                 // warp handles rows wq*8 .. wq*8+7
        for (int rr = 0; rr < 8; rr++) {
            int r  = wq * 8 + rr;
            int qg = q0 + r;                // valid keys: 0..qg
            float* row = Ps + (size_t)r * 260;
            float m = -1e30f;
            for (int j = lane; j <= qg; j += 32) m = fmaxf(m, row[j]);
            #pragma unroll
            for (int off = 16; off > 0; off >>= 1)
                m = fmaxf(m, __shfl_xor_sync(0xffffffffu, m, off));
            float s = 0.0f;
            for (int j = lane; j <= qg; j += 32) {
                float e = __expf(row[j] - m);
                row[j] = e;
                s += e;
            }
            #pragma unroll
            for (int off = 16; off > 0; off >>= 1)
                s += __shfl_xor_sync(0xffffffffu, s, off);
            float inv = 1.0f / s;
            for (int j = lane; j < Kv; j += 32)
                row[j] = (j <= qg) ? row[j] * inv : 0.0f;
        }
    }
    __syncthreads();

    // P -> bf16 hi/lo (rows 64, cols 256; cols >= Kv are zero, harmless)
    {
        __nv_bfloat16* Ph = (__nv_bfloat16*)(smem + AT2_PHI);
        __nv_bfloat16* Pl = (__nv_bfloat16*)(smem + AT2_PLO);
        for (int i = t; i < 64 * 256; i += 256) {
            int r = i >> 8, c = i & 255;
            float p = Ps[r * 260 + c];
            __nv_bfloat16 h = __float2bfloat16(p);
            Ph[r * 264 + c] = h;
            Pl[r * 264 + c] = __float2bfloat16(p - __bfloat162float(h));
        }
    }
    __syncthreads();

    // ---------------- Phase C: O = P V (double-buffered V) -----------------
    const int wnc = (wid >> 1) * 16;        // warp n offset within 64-col chunk
    const int nks = Kv >> 4;                // k16 steps over keys

    auto load_v = [&](int hc, int buf) {
        const unsigned int vb = sb + (buf ? AT2_VB1 : AT2_VB0);
        #pragma unroll
        for (int it = 0; it < 8; it++) {
            int s = t + it * 256;
            int r = s >> 3, j = s & 7;
            if (r < Kv) {
                unsigned int d = (unsigned)(r * ROWB + j * 16);
                size_t go = (size_t)(b * SEQ + r) * HDIM + hc * 64 + j * 8;
                cp16(vb + d, g_vhi + go);
                cp16(vb + 36864u + d, g_vlo + go);
            }
        }
        cp_commit();
    };

    load_v(0, 0);

    for (int hc = 0; hc < 6; hc++) {
        const int buf = hc & 1;
        if (hc + 1 < 6) load_v(hc + 1, buf ^ 1);
        if (hc + 1 < 6) cp_wait1(); else cp_wait0();
        __syncthreads();

        const unsigned int svh = sb + (buf ? AT2_VB1 : AT2_VB0);
        const unsigned int svl = svh + 36864u;

        float oacc[2][2][4];
        #pragma unroll
        for (int mt = 0; mt < 2; mt++)
            #pragma unroll
            for (int nt = 0; nt < 2; nt++)
                #pragma unroll
                for (int q = 0; q < 4; q++) oacc[mt][nt][q] = 0.0f;

        for (int ks = 0; ks < nks; ks++) {
            unsigned int Phf[2][4], Plf[2][4];
            #pragma unroll
            for (int mt = 0; mt < 2; mt++) {
                unsigned int pa = (unsigned)((wm + mt * 16) * 528) + ks * 32 + p_lane;
                ldsm_x4(Phf[mt], sb + AT2_PHI + pa);
                ldsm_x4(Plf[mt], sb + AT2_PLO + pa);
            }
            unsigned int Vh[4], Vl[4];
            unsigned int va = (unsigned)(ks * 16 * ROWB) + (unsigned)(wnc * 2) + v_lane;
            ldsm_x4_t(Vh, svh + va);
            ldsm_x4_t(Vl, svl + va);
            #pragma unroll
            for (int mt = 0; mt < 2; mt++) {
                #pragma unroll
                for (int nt = 0; nt < 2; nt++) {
                    mma_bf16(oacc[mt][nt], Phf[mt], Vh + nt * 2);
                    mma_bf16(oacc[mt][nt], Phf[mt], Vl + nt * 2);
                    mma_bf16(oacc[mt][nt], Plf[mt], Vh + nt * 2);
                }
            }
        }

        // write O chunk
        #pragma unroll
        for (int mt = 0; mt < 2; mt++) {
            int gr = b * SEQ + q0 + wm + mt * 16 + (lane >> 2);
            #pragma unroll
            for (int nt = 0; nt < 2; nt++) {
                int gc = hc * 64 + wnc + nt * 8 + 2 * (lane & 3);
                *(float2*)(Out + (size_t)gr * HDIM + gc) =
                    make_float2(oacc[mt][nt][0], oacc[mt][nt][1]);
                *(float2*)(Out + (size_t)(gr + 8) * HDIM + gc) =
                    make_float2(oacc[mt][nt][2], oacc[mt][nt][3]);
            }
        }
        __syncthreads();
    }
}

// ---------------------------------------------------------------------------
// Launch
// ---------------------------------------------------------------------------
extern "C" void kernel_launch(void* const* d_in, const int* in_sizes, int n_in,
                              void* d_out, int out_size)
{
    const float* x  = (const float*)d_in[0];
    const float* Wq = (const float*)d_in[1];
    const float* Wk = (const float*)d_in[2];
    const float* Wv = (const float*)d_in[3];
    float* out = (float*)d_out;

    cvt_x_kernel<<<(M_TOTAL * CDIM) / 1024, 256>>>(x);
    cvt_w_kernel<<<(3 * CDIM * HDIM) / 256, 256>>>(Wq, Wk, Wv);

    cudaFuncSetAttribute(qkv_mma_kernel, cudaFuncAttributeMaxDynamicSharedMemorySize,
                         QKV_SMEM_BYTES);
    qkv_mma_kernel<<<dim3(9, M_TOTAL / 128), 256, QKV_SMEM_BYTES>>>();

    cudaFuncSetAttribute(attn_mma_kernel, cudaFuncAttributeMaxDynamicSharedMemorySize,
                         AT2_SMEM_BYTES);
    attn_mma_kernel<<<dim3(SEQ / 64, BATCH), 256, AT2_SMEM_BYTES>>>(out);
}

// round 8
// speedup vs baseline: 2.4728x; 1.0941x over previous
#include <cuda_runtime.h>
#include <cuda_bf16.h>
#include <cuda_fp16.h>
#include <math.h>

// Problem constants
#define BATCH 512
#define SEQ   256
#define CDIM  384
#define HDIM  384
#define M_TOTAL (BATCH * SEQ)   // 131072

// ---------------------------------------------------------------------------
// Device scratch (static: runtime allocation is forbidden)
// q/k: bf16 hi/lo pairs. v: fp16 hi/lo pairs (phase C runs in fp16).
// ---------------------------------------------------------------------------
__device__ __nv_bfloat16 g_qhi[(size_t)M_TOTAL * HDIM];
__device__ __nv_bfloat16 g_qlo[(size_t)M_TOTAL * HDIM];
__device__ __nv_bfloat16 g_khi[(size_t)M_TOTAL * HDIM];
__device__ __nv_bfloat16 g_klo[(size_t)M_TOTAL * HDIM];
__device__ __half        g_vhi[(size_t)M_TOTAL * HDIM];
__device__ __half        g_vlo[(size_t)M_TOTAL * HDIM];
// bf16 hi/lo split of X
__device__ __nv_bfloat16 g_xhi[(size_t)M_TOTAL * CDIM];
__device__ __nv_bfloat16 g_xlo[(size_t)M_TOTAL * CDIM];
// bf16 hi/lo of the three weights, TRANSPOSED to [w][n][k]
__device__ __nv_bfloat16 g_whi[(size_t)3 * HDIM * CDIM];
__device__ __nv_bfloat16 g_wlo[(size_t)3 * HDIM * CDIM];

// ---------------------------------------------------------------------------
// PTX helpers (portable to plain sm_103 target — NO tcgen05)
// ---------------------------------------------------------------------------
__device__ __forceinline__ unsigned int smem_u32(const void* p) {
    unsigned int a;
    asm("{ .reg .u64 t; cvta.to.shared.u64 t, %1; cvt.u32.u64 %0, t; }" : "=r"(a) : "l"(p));
    return a;
}
__device__ __forceinline__ void cp16(unsigned int dst, const void* src) {
    asm volatile("cp.async.cg.shared.global [%0], [%1], 16;" :: "r"(dst), "l"(src));
}
__device__ __forceinline__ void cp_commit() {
    asm volatile("cp.async.commit_group;" ::: "memory");
}
__device__ __forceinline__ void cp_wait0() {
    asm volatile("cp.async.wait_group 0;" ::: "memory");
}
__device__ __forceinline__ void cp_wait1() {
    asm volatile("cp.async.wait_group 1;" ::: "memory");
}
__device__ __forceinline__ void ldsm_x4(unsigned int* r, unsigned int addr) {
    asm volatile("ldmatrix.sync.aligned.m8n8.x4.shared.b16 {%0,%1,%2,%3}, [%4];"
                 : "=r"(r[0]), "=r"(r[1]), "=r"(r[2]), "=r"(r[3]) : "r"(addr));
}
__device__ __forceinline__ void ldsm_x4_t(unsigned int* r, unsigned int addr) {
    asm volatile("ldmatrix.sync.aligned.m8n8.x4.trans.shared.b16 {%0,%1,%2,%3}, [%4];"
                 : "=r"(r[0]), "=r"(r[1]), "=r"(r[2]), "=r"(r[3]) : "r"(addr));
}
__device__ __forceinline__ void mma_bf16(float* c, const unsigned int* a,
                                         const unsigned int* b) {
    asm volatile("mma.sync.aligned.m16n8k16.row.col.f32.bf16.bf16.f32 "
                 "{%0,%1,%2,%3}, {%4,%5,%6,%7}, {%8,%9}, {%0,%1,%2,%3};"
                 : "+f"(c[0]), "+f"(c[1]), "+f"(c[2]), "+f"(c[3])
                 : "r"(a[0]), "r"(a[1]), "r"(a[2]), "r"(a[3]), "r"(b[0]), "r"(b[1]));
}
__device__ __forceinline__ void mma_fp16(float* c, const unsigned int* a,
                                         const unsigned int* b) {
    asm volatile("mma.sync.aligned.m16n8k16.row.col.f32.f16.f16.f32 "
                 "{%0,%1,%2,%3}, {%4,%5,%6,%7}, {%8,%9}, {%0,%1,%2,%3};"
                 : "+f"(c[0]), "+f"(c[1]), "+f"(c[2]), "+f"(c[3])
                 : "r"(a[0]), "r"(a[1]), "r"(a[2]), "r"(a[3]), "r"(b[0]), "r"(b[1]));
}
__device__ __forceinline__ void split_pair(float a, float b,
                                           __nv_bfloat162& h2, __nv_bfloat162& l2) {
    __nv_bfloat16 ha = __float2bfloat16(a);
    __nv_bfloat16 hb = __float2bfloat16(b);
    h2 = __halves2bfloat162(ha, hb);
    l2 = __halves2bfloat162(__float2bfloat16(a - __bfloat162float(ha)),
                            __float2bfloat16(b - __bfloat162float(hb)));
}
__device__ __forceinline__ void split_pair_h(float a, float b,
                                             __half2& h2, __half2& l2) {
    __half ha = __float2half_rn(a);
    __half hb = __float2half_rn(b);
    h2 = __halves2half2(ha, hb);
    l2 = __halves2half2(__float2half_rn(a - __half2float(ha)),
                        __float2half_rn(b - __half2float(hb)));
}

// ---------------------------------------------------------------------------
// Prepass 1: X fp32 -> bf16 hi/lo
// ---------------------------------------------------------------------------
__global__ __launch_bounds__(256) void cvt_x_kernel(const float* __restrict__ X)
{
    size_t i = (size_t)blockIdx.x * 256 + threadIdx.x;   // over M*C/4
    float4 v = ((const float4*)X)[i];
    __nv_bfloat162 h0, l0, h1, l1;
    split_pair(v.x, v.y, h0, l0);
    split_pair(v.z, v.w, h1, l1);
    __nv_bfloat162* dh = (__nv_bfloat162*)(g_xhi + 4 * i);
    __nv_bfloat162* dl = (__nv_bfloat162*)(g_xlo + 4 * i);
    dh[0] = h0; dh[1] = h1;
    dl[0] = l0; dl[1] = l1;
}

// ---------------------------------------------------------------------------
// Prepass 2: W fp32 [k][n] -> transposed bf16 hi/lo [w][n][k]
// ---------------------------------------------------------------------------
__global__ __launch_bounds__(256) void cvt_w_kernel(const float* __restrict__ Wq,
                                                    const float* __restrict__ Wk,
                                                    const float* __restrict__ Wv)
{
    int i = blockIdx.x * 256 + threadIdx.x;     // < 3*384*384
    int w = i / (CDIM * HDIM);
    int r = i - w * (CDIM * HDIM);
    int k = r / HDIM;
    int n = r - k * HDIM;
    const float* W = (w == 0) ? Wq : ((w == 1) ? Wk : Wv);
    float v = W[(size_t)k * HDIM + n];
    __nv_bfloat16 h = __float2bfloat16(v);
    size_t o = ((size_t)w * HDIM + n) * CDIM + k;
    g_whi[o] = h;
    g_wlo[o] = __float2bfloat16(v - __bfloat162float(h));
}

// ---------------------------------------------------------------------------
// Kernel: QKV GEMM via mma.sync. CTA 128x128, K chunks of 32, double-buffered,
// 2 CTAs/SM. D = Ahi*Bhi + Ahi*Blo + Alo*Bhi.
// Epilogue: q/k -> bf16 hi/lo; v -> fp16 hi/lo.
// ---------------------------------------------------------------------------
#define ROWB2  80             // padded row stride (32 bf16 = 64B data + 16 pad)
#define TILE2  (128 * ROWB2)  // 10240 bytes per operand tile
#define STG2   (4 * TILE2)    // 40960 bytes per stage
#define QKV_SMEM_BYTES (2 * STG2)   // 81920 -> 2 CTAs/SM
#define NCH2   12

__global__ __launch_bounds__(256, 2) void qkv_mma_kernel()
{
    extern __shared__ char smem[];
    const unsigned int sb = smem_u32(smem);
    const int t    = threadIdx.x;
    const int wid  = t >> 5;
    const int lane = t & 31;

    const int nblk = blockIdx.x;           // 0..8
    const int w    = nblk / 3;             // weight select
    const int n0   = (nblk - w * 3) * 128; // col offset within weight
    const int m0   = blockIdx.y * 128;

    const __nv_bfloat16* whi = g_whi + (size_t)w * HDIM * CDIM;
    const __nv_bfloat16* wlo = g_wlo + (size_t)w * HDIM * CDIM;

    const int wm = (wid & 3) * 32;
    const int wn = (wid >> 2) * 64;

    const unsigned int a_lane = (unsigned)((lane & 15) * ROWB2 + (lane >> 4) * 16);
    const unsigned int b_lane = (unsigned)(((lane & 7) + ((lane >> 4) << 3)) * ROWB2
                                           + ((lane >> 3) & 1) * 16);

    float acc[2][8][4];
    #pragma unroll
    for (int mt = 0; mt < 2; mt++)
        #pragma unroll
        for (int nt = 0; nt < 8; nt++)
            #pragma unroll
            for (int q = 0; q < 4; q++) acc[mt][nt][q] = 0.0f;

    auto load_chunk = [&](int c, int stage) {
        const unsigned int s0 = sb + stage * STG2;
        #pragma unroll
        for (int it = 0; it < 2; it++) {
            int s = t + it * 256;
            int r = s >> 2, j = s & 3;
            unsigned int d = (unsigned)(r * ROWB2 + j * 16);
            size_t ao = (size_t)(m0 + r) * CDIM + c * 32 + j * 8;
            size_t bo = (size_t)(n0 + r) * CDIM + c * 32 + j * 8;
            cp16(s0 + d,             g_xhi + ao);
            cp16(s0 + TILE2 + d,     g_xlo + ao);
            cp16(s0 + 2 * TILE2 + d, whi + bo);
            cp16(s0 + 3 * TILE2 + d, wlo + bo);
        }
        cp_commit();
    };

    load_chunk(0, 0);

    for (int c = 0; c < NCH2; c++) {
        const int stage = c & 1;
        if (c + 1 < NCH2) load_chunk(c + 1, stage ^ 1);

        if (c + 1 < NCH2) cp_wait1(); else cp_wait0();
        __syncthreads();

        const unsigned int sa_hi = sb + stage * STG2;
        const unsigned int sa_lo = sa_hi + TILE2;
        const unsigned int sb_hi = sa_hi + 2 * TILE2;
        const unsigned int sb_lo = sa_hi + 3 * TILE2;

        #pragma unroll
        for (int kk = 0; kk < 2; kk++) {
            const unsigned int koff = kk * 32;
            unsigned int Ahi[2][4], Alo[2][4];
            #pragma unroll
            for (int mt = 0; mt < 2; mt++) {
                unsigned int ab = (unsigned)((wm + mt * 16) * ROWB2) + koff + a_lane;
                ldsm_x4(Ahi[mt], sa_hi + ab);
                ldsm_x4(Alo[mt], sa_lo + ab);
            }
            #pragma unroll
            for (int nt2 = 0; nt2 < 4; nt2++) {
                unsigned int bb = (unsigned)((wn + nt2 * 16) * ROWB2) + koff + b_lane;
                unsigned int Bhi[4], Blo[4];
                ldsm_x4(Bhi, sb_hi + bb);
                ldsm_x4(Blo, sb_lo + bb);
                #pragma unroll
                for (int mt = 0; mt < 2; mt++) {
                    mma_bf16(acc[mt][nt2 * 2 + 0], Ahi[mt], Bhi + 0);
                    mma_bf16(acc[mt][nt2 * 2 + 1], Ahi[mt], Bhi + 2);
                    mma_bf16(acc[mt][nt2 * 2 + 0], Ahi[mt], Blo + 0);
                    mma_bf16(acc[mt][nt2 * 2 + 1], Ahi[mt], Blo + 2);
                    mma_bf16(acc[mt][nt2 * 2 + 0], Alo[mt], Bhi + 0);
                    mma_bf16(acc[mt][nt2 * 2 + 1], Alo[mt], Bhi + 2);
                }
            }
        }
        __syncthreads();
    }

    // Epilogue: q/k -> bf16 hi/lo; v -> fp16 hi/lo
    #pragma unroll
    for (int mt = 0; mt < 2; mt++) {
        int r0 = m0 + wm + mt * 16 + (lane >> 2);
        #pragma unroll
        for (int nt = 0; nt < 8; nt++) {
            int cc = n0 + wn + nt * 8 + 2 * (lane & 3);
            if (w == 2) {
                __half2 h2, l2;
                split_pair_h(acc[mt][nt][0], acc[mt][nt][1], h2, l2);
                *(__half2*)(g_vhi + (size_t)r0 * HDIM + cc) = h2;
                *(__half2*)(g_vlo + (size_t)r0 * HDIM + cc) = l2;
                split_pair_h(acc[mt][nt][2], acc[mt][nt][3], h2, l2);
                *(__half2*)(g_vhi + (size_t)(r0 + 8) * HDIM + cc) = h2;
                *(__half2*)(g_vlo + (size_t)(r0 + 8) * HDIM + cc) = l2;
            } else {
                __nv_bfloat16* ohi = (w == 0) ? g_qhi : g_khi;
                __nv_bfloat16* olo = (w == 0) ? g_qlo : g_klo;
                __nv_bfloat162 h2, l2;
                split_pair(acc[mt][nt][0], acc[mt][nt][1], h2, l2);
                *(__nv_bfloat162*)(ohi + (size_t)r0 * HDIM + cc) = h2;
                *(__nv_bfloat162*)(olo + (size_t)r0 * HDIM + cc) = l2;
                split_pair(acc[mt][nt][2], acc[mt][nt][3], h2, l2);
                *(__nv_bfloat162*)(ohi + (size_t)(r0 + 8) * HDIM + cc) = h2;
                *(__nv_bfloat162*)(olo + (size_t)(r0 + 8) * HDIM + cc) = l2;
            }
        }
    }
}

// ---------------------------------------------------------------------------
// Kernel: causal attention via mma.sync, 2 CTAs/SM (smem 105KB, regs<=128).
// Phase A: S = QK^T, bf16 3-term, Q/K single-buffered per 64-h chunk.
// Phase B: fp32 softmax in smem; P -> SINGLE fp16 (error ~1.4e-4 rms).
// Phase C: O = P V, fp16, V hi/lo (2 MMA terms), single-buffered V chunk.
// Smem overlay (bytes):
//   phase A: QB [0,18432) (hi+lo 9216 each), KB [18432,92160) (hi 36864+lo)
//   phase B: Ps fp32 64x260 at [33792,100352)   (KB dead)
//            PHI fp16 64x264 at [0,33792)       (QB dead)
//   phase C: VB [33792,107520) (hi 36864+lo)    (Ps dead)
// ---------------------------------------------------------------------------
#define ROWB 144
#define AT3_QB   0u
#define AT3_KB   18432u
#define AT3_PS   33792u
#define AT3_PHI  0u
#define AT3_VB   33792u
#define AT3_SMEM_BYTES 107520

__global__ __launch_bounds__(256, 2) void attn_mma_kernel(float* __restrict__ Out)
{
    extern __shared__ char smem[];
    const unsigned int sb = smem_u32(smem);
    const int t    = threadIdx.x;
    const int wid  = t >> 5;
    const int lane = t & 31;
    const int bq   = blockIdx.x;          // 0..3
    const int b    = blockIdx.y;          // 0..511
    const int q0   = bq * 64;
    const int Kv   = (bq + 1) * 64;       // valid keys
    const float scl = rsqrtf((float)HDIM);

    const int wm = (wid & 1) * 32;        // warp m offset (2 m-warps)
    const int wn = (wid >> 1) * 64;       // warp n offset, phase A (4 n-warps)

    const unsigned int a_lane = (unsigned)((lane & 15) * ROWB + (lane >> 4) * 16);
    const unsigned int b_lane = (unsigned)(((lane & 7) + ((lane >> 4) << 3)) * ROWB
                                           + ((lane >> 3) & 1) * 16);
    const unsigned int p_lane = (unsigned)((lane & 15) * 528 + (lane >> 4) * 16);
    const unsigned int v_lane = (unsigned)((lane & 15) * ROWB + (lane >> 4) * 16);

    // ---------------- Phase A: S = Q K^T -----------------------------------
    float sacc[2][8][4];
    #pragma unroll
    for (int mt = 0; mt < 2; mt++)
        #pragma unroll
        for (int nt = 0; nt < 8; nt++)
            #pragma unroll
            for (int q = 0; q < 4; q++) sacc[mt][nt][q] = 0.0f;

    const bool sact = (wn < Kv);

    for (int hc = 0; hc < 6; hc++) {
        // Q chunk: 64 rows x 64 cols hi/lo
        #pragma unroll
        for (int it = 0; it < 2; it++) {
            int s = t + it * 256;
            int r = s >> 3, j = s & 7;
            unsigned int d = (unsigned)(r * ROWB + j * 16);
            size_t go = (size_t)(b * SEQ + q0 + r) * HDIM + hc * 64 + j * 8;
            cp16(sb + AT3_QB + d, g_qhi + go);
            cp16(sb + AT3_QB + 9216u + d, g_qlo + go);
        }
        // K chunk: Kv rows x 64 cols hi/lo
        #pragma unroll
        for (int it = 0; it < 8; it++) {
            int s = t + it * 256;
            int r = s >> 3, j = s & 7;
            if (r < Kv) {
                unsigned int d = (unsigned)(r * ROWB + j * 16);
                size_t go = (size_t)(b * SEQ + r) * HDIM + hc * 64 + j * 8;
                cp16(sb + AT3_KB + d, g_khi + go);
                cp16(sb + AT3_KB + 36864u + d, g_klo + go);
            }
        }
        cp_commit();
        cp_wait0();
        __syncthreads();

        if (sact) {
            const unsigned int sqh = sb + AT3_QB;
            const unsigned int sql = sqh + 9216u;
            const unsigned int skh = sb + AT3_KB;
            const unsigned int skl = skh + 36864u;
            #pragma unroll
            for (int kk = 0; kk < 4; kk++) {
                const unsigned int koff = kk * 32;
                unsigned int Ahi[2][4], Alo[2][4];
                #pragma unroll
                for (int mt = 0; mt < 2; mt++) {
                    unsigned int ab = (unsigned)((wm + mt * 16) * ROWB) + koff + a_lane;
                    ldsm_x4(Ahi[mt], sqh + ab);
                    ldsm_x4(Alo[mt], sql + ab);
                }
                #pragma unroll
                for (int nt2 = 0; nt2 < 4; nt2++) {
                    unsigned int bb = (unsigned)((wn + nt2 * 16) * ROWB) + koff + b_lane;
                    unsigned int Bhi[4], Blo[4];
                    ldsm_x4(Bhi, skh + bb);
                    ldsm_x4(Blo, skl + bb);
                    #pragma unroll
                    for (int mt = 0; mt < 2; mt++) {
                        mma_bf16(sacc[mt][nt2 * 2 + 0], Ahi[mt], Bhi + 0);
                        mma_bf16(sacc[mt][nt2 * 2 + 1], Ahi[mt], Bhi + 2);
                        mma_bf16(sacc[mt][nt2 * 2 + 0], Ahi[mt], Blo + 0);
                        mma_bf16(sacc[mt][nt2 * 2 + 1], Ahi[mt], Blo + 2);
                        mma_bf16(sacc[mt][nt2 * 2 + 0], Alo[mt], Bhi + 0);
                        mma_bf16(sacc[mt][nt2 * 2 + 1], Alo[mt], Bhi + 2);
                    }
                }
            }
        }
        __syncthreads();
    }

    // ---------------- Phase B: scatter S, softmax, P -> fp16 ---------------
    float* Ps = (float*)(smem + AT3_PS);
    #pragma unroll
    for (int mt = 0; mt < 2; mt++) {
        int r = wm + mt * 16 + (lane >> 2);
        #pragma unroll
        for (int nt = 0; nt < 8; nt++) {
            int cc = wn + nt * 8 + 2 * (lane & 3);
            *(float2*)&Ps[r * 260 + cc] =
                make_float2(sacc[mt][nt][0] * scl, sacc[mt][nt][1] * scl);
            *(float2*)&Ps[(r + 8) * 260 + cc] =
                make_float2(sacc[mt][nt][2] * scl, sacc[mt][nt][3] * scl);
        }
    }
    __syncthreads();

    {
        const int wq = wid;                 // warp handles rows wq*8 .. wq*8+7
        for (int rr = 0; rr < 8; rr++) {
            int r  = wq * 8 + rr;
            int qg = q0 + r;                // valid keys: 0..qg
            float* row = Ps + (size_t)r * 260;
            float m = -1e30f;
            for (int j = lane; j <= qg; j += 32) m = fmaxf(m, row[j]);
            #pragma unroll
            for (int off = 16; off > 0; off >>= 1)
                m = fmaxf(m, __shfl_xor_sync(0xffffffffu, m, off));
            float s = 0.0f;
            for (int j = lane; j <= qg; j += 32) {
                float e = __expf(row[j] - m);
                row[j] = e;
                s += e;
            }
            #pragma unroll
            for (int off = 16; off > 0; off >>= 1)
                s += __shfl_xor_sync(0xffffffffu, s, off);
            float inv = 1.0f / s;
            for (int j = lane; j < Kv; j += 32)
                row[j] = (j <= qg) ? row[j] * inv : 0.0f;
        }
    }
    __syncthreads();

    // P -> single fp16 (reads Ps at [33792,...), writes PHI at [0,33792))
    {
        __half* Ph = (__half*)(smem + AT3_PHI);
        for (int i = t; i < 64 * 256; i += 256) {
            int r = i >> 8, c = i & 255;
            Ph[r * 264 + c] = __float2half_rn(Ps[r * 260 + c]);
        }
    }
    __syncthreads();

    // ---------------- Phase C: O = P V (fp16, V hi/lo) ---------------------
    const int wnc = (wid >> 1) * 16;        // warp n offset within 64-col chunk
    const int nks = Kv >> 4;                // k16 steps over keys

    for (int hc = 0; hc < 6; hc++) {
        // V chunk: Kv rows x 64 cols hi/lo (overlays dead Ps)
        #pragma unroll
        for (int it = 0; it < 8; it++) {
            int s = t + it * 256;
            int r = s >> 3, j = s & 7;
            if (r < Kv) {
                unsigned int d = (unsigned)(r * ROWB + j * 16);
                size_t go = (size_t)(b * SEQ + r) * HDIM + hc * 64 + j * 8;
                cp16(sb + AT3_VB + d, g_vhi + go);
                cp16(sb + AT3_VB + 36864u + d, g_vlo + go);
            }
        }
        cp_commit();
        cp_wait0();
        __syncthreads();

        const unsigned int svh = sb + AT3_VB;
        const unsigned int svl = svh + 36864u;

        float oacc[2][2][4];
        #pragma unroll
        for (int mt = 0; mt < 2; mt++)
            #pragma unroll
            for (int nt = 0; nt < 2; nt++)
                #pragma unroll
                for (int q = 0; q < 4; q++) oacc[mt][nt][q] = 0.0f;

        for (int ks = 0; ks < nks; ks++) {
            unsigned int Phf[2][4];
            #pragma unroll
            for (int mt = 0; mt < 2; mt++) {
                unsigned int pa = (unsigned)((wm + mt * 16) * 528) + ks * 32 + p_lane;
                ldsm_x4(Phf[mt], sb + AT3_PHI + pa);
            }
            unsigned int Vh[4], Vl[4];
            unsigned int va = (unsigned)(ks * 16 * ROWB) + (unsigned)(wnc * 2) + v_lane;
            ldsm_x4_t(Vh, svh + va);
            ldsm_x4_t(Vl, svl + va);
            #pragma unroll
            for (int mt = 0; mt < 2; mt++) {
                #pragma unroll
                for (int nt = 0; nt < 2; nt++) {
                    mma_fp16(oacc[mt][nt], Phf[mt], Vh + nt * 2);
                    mma_fp16(oacc[mt][nt], Phf[mt], Vl + nt * 2);
                }
            }
        }

        // write O chunk
        #pragma unroll
        for (int mt = 0; mt < 2; mt++) {
            int gr = b * SEQ + q0 + wm + mt * 16 + (lane >> 2);
            #pragma unroll
            for (int nt = 0; nt < 2; nt++) {
                int gc = hc * 64 + wnc + nt * 8 + 2 * (lane & 3);
                *(float2*)(Out + (size_t)gr * HDIM + gc) =
                    make_float2(oacc[mt][nt][0], oacc[mt][nt][1]);
                *(float2*)(Out + (size_t)(gr + 8) * HDIM + gc) =
                    make_float2(oacc[mt][nt][2], oacc[mt][nt][3]);
            }
        }
        __syncthreads();
    }
}

// ---------------------------------------------------------------------------
// Launch
// ---------------------------------------------------------------------------
extern "C" void kernel_launch(void* const* d_in, const int* in_sizes, int n_in,
                              void* d_out, int out_size)
{
    const float* x  = (const float*)d_in[0];
    const float* Wq = (const float*)d_in[1];
    const float* Wk = (const float*)d_in[2];
    const float* Wv = (const float*)d_in[3];
    float* out = (float*)d_out;

    cvt_x_kernel<<<(M_TOTAL * CDIM) / 1024, 256>>>(x);
    cvt_w_kernel<<<(3 * CDIM * HDIM) / 256, 256>>>(Wq, Wk, Wv);

    cudaFuncSetAttribute(qkv_mma_kernel, cudaFuncAttributeMaxDynamicSharedMemorySize,
                         QKV_SMEM_BYTES);
    qkv_mma_kernel<<<dim3(9, M_TOTAL / 128), 256, QKV_SMEM_BYTES>>>();

    cudaFuncSetAttribute(attn_mma_kernel, cudaFuncAttributeMaxDynamicSharedMemorySize,
                         AT3_SMEM_BYTES);
    attn_mma_kernel<<<dim3(SEQ / 64, BATCH), 256, AT3_SMEM_BYTES>>>(out);
}

// round 9
// speedup vs baseline: 2.7128x; 1.0971x over previous
#include <cuda_runtime.h>
#include <cuda_bf16.h>
#include <cuda_fp16.h>
#include <math.h>

// Problem constants
#define BATCH 512
#define SEQ   256
#define CDIM  384
#define HDIM  384
#define M_TOTAL (BATCH * SEQ)   // 131072

// ---------------------------------------------------------------------------
// Device scratch (static: runtime allocation is forbidden)
// q/k: bf16 hi/lo pairs. v: single fp16 (phase C is 1-term fp16).
// ---------------------------------------------------------------------------
__device__ __nv_bfloat16 g_qhi[(size_t)M_TOTAL * HDIM];
__device__ __nv_bfloat16 g_qlo[(size_t)M_TOTAL * HDIM];
__device__ __nv_bfloat16 g_khi[(size_t)M_TOTAL * HDIM];
__device__ __nv_bfloat16 g_klo[(size_t)M_TOTAL * HDIM];
__device__ __half        g_vhi[(size_t)M_TOTAL * HDIM];
// bf16 hi/lo split of X
__device__ __nv_bfloat16 g_xhi[(size_t)M_TOTAL * CDIM];
__device__ __nv_bfloat16 g_xlo[(size_t)M_TOTAL * CDIM];
// bf16 hi/lo of the three weights, TRANSPOSED to [w][n][k]
__device__ __nv_bfloat16 g_whi[(size_t)3 * HDIM * CDIM];
__device__ __nv_bfloat16 g_wlo[(size_t)3 * HDIM * CDIM];

// ---------------------------------------------------------------------------
// PTX helpers (portable to plain sm_103 target — NO tcgen05)
// ---------------------------------------------------------------------------
__device__ __forceinline__ unsigned int smem_u32(const void* p) {
    unsigned int a;
    asm("{ .reg .u64 t; cvta.to.shared.u64 t, %1; cvt.u32.u64 %0, t; }" : "=r"(a) : "l"(p));
    return a;
}
__device__ __forceinline__ void cp16(unsigned int dst, const void* src) {
    asm volatile("cp.async.cg.shared.global [%0], [%1], 16;" :: "r"(dst), "l"(src));
}
__device__ __forceinline__ void cp_commit() {
    asm volatile("cp.async.commit_group;" ::: "memory");
}
__device__ __forceinline__ void cp_wait0() {
    asm volatile("cp.async.wait_group 0;" ::: "memory");
}
__device__ __forceinline__ void cp_wait1() {
    asm volatile("cp.async.wait_group 1;" ::: "memory");
}
__device__ __forceinline__ void ldsm_x4(unsigned int* r, unsigned int addr) {
    asm volatile("ldmatrix.sync.aligned.m8n8.x4.shared.b16 {%0,%1,%2,%3}, [%4];"
                 : "=r"(r[0]), "=r"(r[1]), "=r"(r[2]), "=r"(r[3]) : "r"(addr));
}
__device__ __forceinline__ void ldsm_x4_t(unsigned int* r, unsigned int addr) {
    asm volatile("ldmatrix.sync.aligned.m8n8.x4.trans.shared.b16 {%0,%1,%2,%3}, [%4];"
                 : "=r"(r[0]), "=r"(r[1]), "=r"(r[2]), "=r"(r[3]) : "r"(addr));
}
__device__ __forceinline__ void mma_bf16(float* c, const unsigned int* a,
                                         const unsigned int* b) {
    asm volatile("mma.sync.aligned.m16n8k16.row.col.f32.bf16.bf16.f32 "
                 "{%0,%1,%2,%3}, {%4,%5,%6,%7}, {%8,%9}, {%0,%1,%2,%3};"
                 : "+f"(c[0]), "+f"(c[1]), "+f"(c[2]), "+f"(c[3])
                 : "r"(a[0]), "r"(a[1]), "r"(a[2]), "r"(a[3]), "r"(b[0]), "r"(b[1]));
}
__device__ __forceinline__ void mma_fp16(float* c, const unsigned int* a,
                                         const unsigned int* b) {
    asm volatile("mma.sync.aligned.m16n8k16.row.col.f32.f16.f16.f32 "
                 "{%0,%1,%2,%3}, {%4,%5,%6,%7}, {%8,%9}, {%0,%1,%2,%3};"
                 : "+f"(c[0]), "+f"(c[1]), "+f"(c[2]), "+f"(c[3])
                 : "r"(a[0]), "r"(a[1]), "r"(a[2]), "r"(a[3]), "r"(b[0]), "r"(b[1]));
}
__device__ __forceinline__ void split_pair(float a, float b,
                                           __nv_bfloat162& h2, __nv_bfloat162& l2) {
    __nv_bfloat16 ha = __float2bfloat16(a);
    __nv_bfloat16 hb = __float2bfloat16(b);
    h2 = __halves2bfloat162(ha, hb);
    l2 = __halves2bfloat162(__float2bfloat16(a - __bfloat162float(ha)),
                            __float2bfloat16(b - __bfloat162float(hb)));
}

// ---------------------------------------------------------------------------
// Prepass 1: X fp32 -> bf16 hi/lo
// ---------------------------------------------------------------------------
__global__ __launch_bounds__(256) void cvt_x_kernel(const float* __restrict__ X)
{
    size_t i = (size_t)blockIdx.x * 256 + threadIdx.x;   // over M*C/4
    float4 v = ((const float4*)X)[i];
    __nv_bfloat162 h0, l0, h1, l1;
    split_pair(v.x, v.y, h0, l0);
    split_pair(v.z, v.w, h1, l1);
    __nv_bfloat162* dh = (__nv_bfloat162*)(g_xhi + 4 * i);
    __nv_bfloat162* dl = (__nv_bfloat162*)(g_xlo + 4 * i);
    dh[0] = h0; dh[1] = h1;
    dl[0] = l0; dl[1] = l1;
}

// ---------------------------------------------------------------------------
// Prepass 2: W fp32 [k][n] -> transposed bf16 hi/lo [w][n][k]
// ---------------------------------------------------------------------------
__global__ __launch_bounds__(256) void cvt_w_kernel(const float* __restrict__ Wq,
                                                    const float* __restrict__ Wk,
                                                    const float* __restrict__ Wv)
{
    int i = blockIdx.x * 256 + threadIdx.x;     // < 3*384*384
    int w = i / (CDIM * HDIM);
    int r = i - w * (CDIM * HDIM);
    int k = r / HDIM;
    int n = r - k * HDIM;
    const float* W = (w == 0) ? Wq : ((w == 1) ? Wk : Wv);
    float v = W[(size_t)k * HDIM + n];
    __nv_bfloat16 h = __float2bfloat16(v);
    size_t o = ((size_t)w * HDIM + n) * CDIM + k;
    g_whi[o] = h;
    g_wlo[o] = __float2bfloat16(v - __bfloat162float(h));
}

// ---------------------------------------------------------------------------
// Kernel: QKV GEMM via mma.sync. CTA 128x128, K chunks of 64, 2 CTAs/SM.
// Asymmetric buffering: A (X) single-buffered, B (weights) double-buffered.
// Per chunk only the A load (37KB) is exposed; B(c+2) streams during compute.
// Commit-group order per chunk: [A(c+1)] then [B(c+2)] so wait_group 1 at the
// loop head releases exactly {B(c+1), A(c+1)}.
// Smem: AHI 0 | ALO 18432 | B buf0 36864 | B buf1 73728  (110592 B/CTA)
// ---------------------------------------------------------------------------
#define ROWB   144            // padded row stride (64 bf16 = 128B data + 16 pad)
#define QTILE  (128 * ROWB)   // 18432 bytes per operand tile
#define QKV_SMEM_BYTES 110592
#define NCHK   6

__global__ __launch_bounds__(256, 2) void qkv_mma_kernel()
{
    extern __shared__ char smem[];
    const unsigned int sb = smem_u32(smem);
    const int t    = threadIdx.x;
    const int wid  = t >> 5;
    const int lane = t & 31;

    const int nblk = blockIdx.x;           // 0..8
    const int w    = nblk / 3;             // weight select
    const int n0   = (nblk - w * 3) * 128; // col offset within weight
    const int m0   = blockIdx.y * 128;

    const __nv_bfloat16* whi = g_whi + (size_t)w * HDIM * CDIM;
    const __nv_bfloat16* wlo = g_wlo + (size_t)w * HDIM * CDIM;

    const int wm = (wid & 3) * 32;
    const int wn = (wid >> 2) * 64;

    const unsigned int a_lane = (unsigned)((lane & 15) * ROWB + (lane >> 4) * 16);
    const unsigned int b_lane = (unsigned)(((lane & 7) + ((lane >> 4) << 3)) * ROWB
                                           + ((lane >> 3) & 1) * 16);

    float acc[2][8][4];
    #pragma unroll
    for (int mt = 0; mt < 2; mt++)
        #pragma unroll
        for (int nt = 0; nt < 8; nt++)
            #pragma unroll
            for (int q = 0; q < 4; q++) acc[mt][nt][q] = 0.0f;

    // A tile loader (hi+lo), own commit group
    auto load_a = [&](int c) {
        #pragma unroll
        for (int it = 0; it < 4; it++) {
            int s = t + it * 256;
            int r = s >> 3, j = s & 7;
            unsigned int d = (unsigned)(r * ROWB + j * 16);
            size_t go = (size_t)(m0 + r) * CDIM + c * 64 + j * 8;
            cp16(sb + d,         g_xhi + go);
            cp16(sb + QTILE + d, g_xlo + go);
        }
        cp_commit();
    };
    // B tile loader (hi+lo) into buf, own commit group
    auto load_b = [&](int c, int buf) {
        const unsigned int b0 = sb + 36864u + (unsigned)buf * 36864u;
        #pragma unroll
        for (int it = 0; it < 4; it++) {
            int s = t + it * 256;
            int r = s >> 3, j = s & 7;
            unsigned int d = (unsigned)(r * ROWB + j * 16);
            size_t go = (size_t)(n0 + r) * CDIM + c * 64 + j * 8;
            cp16(b0 + d,         whi + go);
            cp16(b0 + 18432u + d, wlo + go);
        }
        cp_commit();
    };

    // Prologue: group0 = A(0)+B(0)? -> keep groups simple: [A0+B0], [B1]
    {
        #pragma unroll
        for (int it = 0; it < 4; it++) {
            int s = t + it * 256;
            int r = s >> 3, j = s & 7;
            unsigned int d = (unsigned)(r * ROWB + j * 16);
            size_t ao = (size_t)(m0 + r) * CDIM + j * 8;
            size_t bo = (size_t)(n0 + r) * CDIM + j * 8;
            cp16(sb + d,          g_xhi + ao);
            cp16(sb + QTILE + d,  g_xlo + ao);
            cp16(sb + 36864u + d, whi + bo);
            cp16(sb + 36864u + 18432u + d, wlo + bo);
        }
        cp_commit();           // group: A(0)+B(0)
        load_b(1, 1);          // group: B(1)
    }

    for (int c = 0; c < NCHK; c++) {
        // release everything except the newest pending B group
        if (c + 1 < NCHK) cp_wait1(); else cp_wait0();
        __syncthreads();

        const unsigned int sa_hi = sb;
        const unsigned int sa_lo = sb + QTILE;
        const unsigned int sb_hi = sb + 36864u + (unsigned)(c & 1) * 36864u;
        const unsigned int sb_lo = sb_hi + 18432u;

        #pragma unroll
        for (int kk = 0; kk < 4; kk++) {
            const unsigned int koff = kk * 32;
            unsigned int Ahi[2][4], Alo[2][4];
            #pragma unroll
            for (int mt = 0; mt < 2; mt++) {
                unsigned int ab = (unsigned)((wm + mt * 16) * ROWB) + koff + a_lane;
                ldsm_x4(Ahi[mt], sa_hi + ab);
                ldsm_x4(Alo[mt], sa_lo + ab);
            }
            #pragma unroll
            for (int nt2 = 0; nt2 < 4; nt2++) {
                unsigned int bb = (unsigned)((wn + nt2 * 16) * ROWB) + koff + b_lane;
                unsigned int Bhi[4], Blo[4];
                ldsm_x4(Bhi, sb_hi + bb);
                ldsm_x4(Blo, sb_lo + bb);
                #pragma unroll
                for (int mt = 0; mt < 2; mt++) {
                    mma_bf16(acc[mt][nt2 * 2 + 0], Ahi[mt], Bhi + 0);
                    mma_bf16(acc[mt][nt2 * 2 + 1], Ahi[mt], Bhi + 2);
                    mma_bf16(acc[mt][nt2 * 2 + 0], Ahi[mt], Blo + 0);
                    mma_bf16(acc[mt][nt2 * 2 + 1], Ahi[mt], Blo + 2);
                    mma_bf16(acc[mt][nt2 * 2 + 0], Alo[mt], Bhi + 0);
                    mma_bf16(acc[mt][nt2 * 2 + 1], Alo[mt], Bhi + 2);
                }
            }
        }
        __syncthreads();   // all warps done with A buffer + B buf (c&1)

        if (c + 1 < NCHK) load_a(c + 1);         // group [A(c+1)]
        if (c + 2 < NCHK) load_b(c + 2, c & 1);  // group [B(c+2)] into freed buf
    }

    // Epilogue: q/k -> bf16 hi/lo; v -> single fp16
    #pragma unroll
    for (int mt = 0; mt < 2; mt++) {
        int r0 = m0 + wm + mt * 16 + (lane >> 2);
        #pragma unroll
        for (int nt = 0; nt < 8; nt++) {
            int cc = n0 + wn + nt * 8 + 2 * (lane & 3);
            if (w == 2) {
                *(__half2*)(g_vhi + (size_t)r0 * HDIM + cc) =
                    __floats2half2_rn(acc[mt][nt][0], acc[mt][nt][1]);
                *(__half2*)(g_vhi + (size_t)(r0 + 8) * HDIM + cc) =
                    __floats2half2_rn(acc[mt][nt][2], acc[mt][nt][3]);
            } else {
                __nv_bfloat16* ohi = (w == 0) ? g_qhi : g_khi;
                __nv_bfloat16* olo = (w == 0) ? g_qlo : g_klo;
                __nv_bfloat162 h2, l2;
                split_pair(acc[mt][nt][0], acc[mt][nt][1], h2, l2);
                *(__nv_bfloat162*)(ohi + (size_t)r0 * HDIM + cc) = h2;
                *(__nv_bfloat162*)(olo + (size_t)r0 * HDIM + cc) = l2;
                split_pair(acc[mt][nt][2], acc[mt][nt][3], h2, l2);
                *(__nv_bfloat162*)(ohi + (size_t)(r0 + 8) * HDIM + cc) = h2;
                *(__nv_bfloat162*)(olo + (size_t)(r0 + 8) * HDIM + cc) = l2;
            }
        }
    }
}

// ---------------------------------------------------------------------------
// Kernel: causal attention via mma.sync, 2 CTAs/SM (smem 100KB, regs<=128).
// Phase A: S = QK^T, bf16 3-term.  Phase B: fp32 softmax; P -> single fp16.
// Phase C: O = P V, fp16 1-term (V single fp16).
// Smem overlay (bytes):
//   phase A: QB [0,18432) (hi/lo 9216), KB [18432,92160) (hi 36864 + lo)
//   phase B: Ps fp32 64x260 at [33792,100352); PHI fp16 64x264 at [0,33792)
//   phase C: VB fp16 at [33792,70656)
// ---------------------------------------------------------------------------
#define AT3_QB   0u
#define AT3_KB   18432u
#define AT3_PS   33792u
#define AT3_PHI  0u
#define AT3_VB   33792u
#define AT3_SMEM_BYTES 100352

__global__ __launch_bounds__(256, 2) void attn_mma_kernel(float* __restrict__ Out)
{
    extern __shared__ char smem[];
    const unsigned int sb = smem_u32(smem);
    const int t    = threadIdx.x;
    const int wid  = t >> 5;
    const int lane = t & 31;
    const int bq   = blockIdx.x;          // 0..3
    const int b    = blockIdx.y;          // 0..511
    const int q0   = bq * 64;
    const int Kv   = (bq + 1) * 64;       // valid keys
    const float scl = rsqrtf((float)HDIM);

    const int wm = (wid & 1) * 32;        // warp m offset (2 m-warps)
    const int wn = (wid >> 1) * 64;       // warp n offset, phase A (4 n-warps)

    const unsigned int a_lane = (unsigned)((lane & 15) * ROWB + (lane >> 4) * 16);
    const unsigned int b_lane = (unsigned)(((lane & 7) + ((lane >> 4) << 3)) * ROWB
                                           + ((lane >> 3) & 1) * 16);
    const unsigned int p_lane = (unsigned)((lane & 15) * 528 + (lane >> 4) * 16);
    const unsigned int v_lane = (unsigned)((lane & 15) * ROWB + (lane >> 4) * 16);

    // ---------------- Phase A: S = Q K^T -----------------------------------
    float sacc[2][8][4];
    #pragma unroll
    for (int mt = 0; mt < 2; mt++)
        #pragma unroll
        for (int nt = 0; nt < 8; nt++)
            #pragma unroll
            for (int q = 0; q < 4; q++) sacc[mt][nt][q] = 0.0f;

    const bool sact = (wn < Kv);

    for (int hc = 0; hc < 6; hc++) {
        // Q chunk: 64 rows x 64 cols hi/lo
        #pragma unroll
        for (int it = 0; it < 2; it++) {
            int s = t + it * 256;
            int r = s >> 3, j = s & 7;
            unsigned int d = (unsigned)(r * ROWB + j * 16);
            size_t go = (size_t)(b * SEQ + q0 + r) * HDIM + hc * 64 + j * 8;
            cp16(sb + AT3_QB + d, g_qhi + go);
            cp16(sb + AT3_QB + 9216u + d, g_qlo + go);
        }
        // K chunk: Kv rows x 64 cols hi/lo
        #pragma unroll
        for (int it = 0; it < 8; it++) {
            int s = t + it * 256;
            int r = s >> 3, j = s & 7;
            if (r < Kv) {
                unsigned int d = (unsigned)(r * ROWB + j * 16);
                size_t go = (size_t)(b * SEQ + r) * HDIM + hc * 64 + j * 8;
                cp16(sb + AT3_KB + d, g_khi + go);
                cp16(sb + AT3_KB + 36864u + d, g_klo + go);
            }
        }
        cp_commit();
        cp_wait0();
        __syncthreads();

        if (sact) {
            const unsigned int sqh = sb + AT3_QB;
            const unsigned int sql = sqh + 9216u;
            const unsigned int skh = sb + AT3_KB;
            const unsigned int skl = skh + 36864u;
            #pragma unroll
            for (int kk = 0; kk < 4; kk++) {
                const unsigned int koff = kk * 32;
                unsigned int Ahi[2][4], Alo[2][4];
                #pragma unroll
                for (int mt = 0; mt < 2; mt++) {
                    unsigned int ab = (unsigned)((wm + mt * 16) * ROWB) + koff + a_lane;
                    ldsm_x4(Ahi[mt], sqh + ab);
                    ldsm_x4(Alo[mt], sql + ab);
                }
                #pragma unroll
                for (int nt2 = 0; nt2 < 4; nt2++) {
                    unsigned int bb = (unsigned)((wn + nt2 * 16) * ROWB) + koff + b_lane;
                    unsigned int Bhi[4], Blo[4];
                    ldsm_x4(Bhi, skh + bb);
                    ldsm_x4(Blo, skl + bb);
                    #pragma unroll
                    for (int mt = 0; mt < 2; mt++) {
                        mma_bf16(sacc[mt][nt2 * 2 + 0], Ahi[mt], Bhi + 0);
                        mma_bf16(sacc[mt][nt2 * 2 + 1], Ahi[mt], Bhi + 2);
                        mma_bf16(sacc[mt][nt2 * 2 + 0], Ahi[mt], Blo + 0);
                        mma_bf16(sacc[mt][nt2 * 2 + 1], Ahi[mt], Blo + 2);
                        mma_bf16(sacc[mt][nt2 * 2 + 0], Alo[mt], Bhi + 0);
                        mma_bf16(sacc[mt][nt2 * 2 + 1], Alo[mt], Bhi + 2);
                    }
                }
            }
        }
        __syncthreads();
    }

    // ---------------- Phase B: scatter S, softmax, P -> fp16 ---------------
    float* Ps = (float*)(smem + AT3_PS);
    #pragma unroll
    for (int mt = 0; mt < 2; mt++) {
        int r = wm + mt * 16 + (lane >> 2);
        #pragma unroll
        for (int nt = 0; nt < 8; nt++) {
            int cc = wn + nt * 8 + 2 * (lane & 3);
            *(float2*)&Ps[r * 260 + cc] =
                make_float2(sacc[mt][nt][0] * scl, sacc[mt][nt][1] * scl);
            *(float2*)&Ps[(r + 8) * 260 + cc] =
                make_float2(sacc[mt][nt][2] * scl, sacc[mt][nt][3] * scl);
        }
    }
    __syncthreads();

    {
        const int wq = wid;                 // warp handles rows wq*8 .. wq*8+7
        for (int rr = 0; rr < 8; rr++) {
            int r  = wq * 8 + rr;
            int qg = q0 + r;                // valid keys: 0..qg
            float* row = Ps + (size_t)r * 260;
            float m = -1e30f;
            for (int j = lane; j <= qg; j += 32) m = fmaxf(m, row[j]);
            #pragma unroll
            for (int off = 16; off > 0; off >>= 1)
                m = fmaxf(m, __shfl_xor_sync(0xffffffffu, m, off));
            float s = 0.0f;
            for (int j = lane; j <= qg; j += 32) {
                float e = __expf(row[j] - m);
                row[j] = e;
                s += e;
            }
            #pragma unroll
            for (int off = 16; off > 0; off >>= 1)
                s += __shfl_xor_sync(0xffffffffu, s, off);
            float inv = 1.0f / s;
            for (int j = lane; j < Kv; j += 32)
                row[j] = (j <= qg) ? row[j] * inv : 0.0f;
        }
    }
    __syncthreads();

    // P -> single fp16 (reads Ps at [33792,...), writes PHI at [0,33792))
    {
        __half* Ph = (__half*)(smem + AT3_PHI);
        for (int i = t; i < 64 * 256; i += 256) {
            int r = i >> 8, c = i & 255;
            Ph[r * 264 + c] = __float2half_rn(Ps[r * 260 + c]);
        }
    }
    __syncthreads();

    // ---------------- Phase C: O = P V (fp16, 1-term V) --------------------
    const int wnc = (wid >> 1) * 16;        // warp n offset within 64-col chunk
    const int nks = Kv >> 4;                // k16 steps over keys

    for (int hc = 0; hc < 6; hc++) {
        // V chunk: Kv rows x 64 cols (single fp16; overlays dead Ps)
        #pragma unroll
        for (int it = 0; it < 8; it++) {
            int s = t + it * 256;
            int r = s >> 3, j = s & 7;
            if (r < Kv) {
                unsigned int d = (unsigned)(r * ROWB + j * 16);
                size_t go = (size_t)(b * SEQ + r) * HDIM + hc * 64 + j * 8;
                cp16(sb + AT3_VB + d, g_vhi + go);
            }
        }
        cp_commit();
        cp_wait0();
        __syncthreads();

        const unsigned int svh = sb + AT3_VB;

        float oacc[2][2][4];
        #pragma unroll
        for (int mt = 0; mt < 2; mt++)
            #pragma unroll
            for (int nt = 0; nt < 2; nt++)
                #pragma unroll
                for (int q = 0; q < 4; q++) oacc[mt][nt][q] = 0.0f;

        for (int ks = 0; ks < nks; ks++) {
            unsigned int Phf[2][4];
            #pragma unroll
            for (int mt = 0; mt < 2; mt++) {
                unsigned int pa = (unsigned)((wm + mt * 16) * 528) + ks * 32 + p_lane;
                ldsm_x4(Phf[mt], sb + AT3_PHI + pa);
            }
            unsigned int Vh[4];
            unsigned int va = (unsigned)(ks * 16 * ROWB) + (unsigned)(wnc * 2) + v_lane;
            ldsm_x4_t(Vh, svh + va);
            #pragma unroll
            for (int mt = 0; mt < 2; mt++) {
                #pragma unroll
                for (int nt = 0; nt < 2; nt++) {
                    mma_fp16(oacc[mt][nt], Phf[mt], Vh + nt * 2);
                }
            }
        }

        // write O chunk
        #pragma unroll
        for (int mt = 0; mt < 2; mt++) {
            int gr = b * SEQ + q0 + wm + mt * 16 + (lane >> 2);
            #pragma unroll
            for (int nt = 0; nt < 2; nt++) {
                int gc = hc * 64 + wnc + nt * 8 + 2 * (lane & 3);
                *(float2*)(Out + (size_t)gr * HDIM + gc) =
                    make_float2(oacc[mt][nt][0], oacc[mt][nt][1]);
                *(float2*)(Out + (size_t)(gr + 8) * HDIM + gc) =
                    make_float2(oacc[mt][nt][2], oacc[mt][nt][3]);
            }
        }
        __syncthreads();
    }
}

// ---------------------------------------------------------------------------
// Launch
// ---------------------------------------------------------------------------
extern "C" void kernel_launch(void* const* d_in, const int* in_sizes, int n_in,
                              void* d_out, int out_size)
{
    const float* x  = (const float*)d_in[0];
    const float* Wq = (const float*)d_in[1];
    const float* Wk = (const float*)d_in[2];
    const float* Wv = (const float*)d_in[3];
    float* out = (float*)d_out;

    cvt_x_kernel<<<(M_TOTAL * CDIM) / 1024, 256>>>(x);
    cvt_w_kernel<<<(3 * CDIM * HDIM) / 256, 256>>>(Wq, Wk, Wv);

    cudaFuncSetAttribute(qkv_mma_kernel, cudaFuncAttributeMaxDynamicSharedMemorySize,
                         QKV_SMEM_BYTES);
    qkv_mma_kernel<<<dim3(9, M_TOTAL / 128), 256, QKV_SMEM_BYTES>>>();

    cudaFuncSetAttribute(attn_mma_kernel, cudaFuncAttributeMaxDynamicSharedMemorySize,
                         AT3_SMEM_BYTES);
    attn_mma_kernel<<<dim3(SEQ / 64, BATCH), 256, AT3_SMEM_BYTES>>>(out);
}

// round 10
// speedup vs baseline: 5.1543x; 1.9000x over previous
#include <cuda_runtime.h>
#include <cuda_bf16.h>
#include <cuda_fp16.h>
#include <math.h>

// Problem constants
#define BATCH 512
#define SEQ   256
#define CDIM  384
#define HDIM  384
#define M_TOTAL (BATCH * SEQ)   // 131072

// ---------------------------------------------------------------------------
// Device scratch (static: runtime allocation is forbidden)
// q/k/v single fp16 (fp16 MMA is exact given fp16 inputs; quantization 1.4e-4)
// ---------------------------------------------------------------------------
__device__ __half g_q[(size_t)M_TOTAL * HDIM];
__device__ __half g_k[(size_t)M_TOTAL * HDIM];
__device__ __half g_v[(size_t)M_TOTAL * HDIM];
__device__ __half g_x[(size_t)M_TOTAL * CDIM];          // X as fp16
__device__ __half g_w[(size_t)3 * HDIM * CDIM];         // W transposed [w][n][k], fp16

// ---------------------------------------------------------------------------
// PTX helpers (portable to plain sm_103 target — NO tcgen05)
// ---------------------------------------------------------------------------
__device__ __forceinline__ unsigned int smem_u32(const void* p) {
    unsigned int a;
    asm("{ .reg .u64 t; cvta.to.shared.u64 t, %1; cvt.u32.u64 %0, t; }" : "=r"(a) : "l"(p));
    return a;
}
__device__ __forceinline__ void cp16(unsigned int dst, const void* src) {
    asm volatile("cp.async.cg.shared.global [%0], [%1], 16;" :: "r"(dst), "l"(src));
}
__device__ __forceinline__ void cp_commit() {
    asm volatile("cp.async.commit_group;" ::: "memory");
}
__device__ __forceinline__ void cp_wait0() {
    asm volatile("cp.async.wait_group 0;" ::: "memory");
}
__device__ __forceinline__ void cp_wait1() {
    asm volatile("cp.async.wait_group 1;" ::: "memory");
}
__device__ __forceinline__ void ldsm_x4(unsigned int* r, unsigned int addr) {
    asm volatile("ldmatrix.sync.aligned.m8n8.x4.shared.b16 {%0,%1,%2,%3}, [%4];"
                 : "=r"(r[0]), "=r"(r[1]), "=r"(r[2]), "=r"(r[3]) : "r"(addr));
}
__device__ __forceinline__ void ldsm_x4_t(unsigned int* r, unsigned int addr) {
    asm volatile("ldmatrix.sync.aligned.m8n8.x4.trans.shared.b16 {%0,%1,%2,%3}, [%4];"
                 : "=r"(r[0]), "=r"(r[1]), "=r"(r[2]), "=r"(r[3]) : "r"(addr));
}
__device__ __forceinline__ void mma_fp16(float* c, const unsigned int* a,
                                         const unsigned int* b) {
    asm volatile("mma.sync.aligned.m16n8k16.row.col.f32.f16.f16.f32 "
                 "{%0,%1,%2,%3}, {%4,%5,%6,%7}, {%8,%9}, {%0,%1,%2,%3};"
                 : "+f"(c[0]), "+f"(c[1]), "+f"(c[2]), "+f"(c[3])
                 : "r"(a[0]), "r"(a[1]), "r"(a[2]), "r"(a[3]), "r"(b[0]), "r"(b[1]));
}

// ---------------------------------------------------------------------------
// Prepass 1: X fp32 -> fp16
// ---------------------------------------------------------------------------
__global__ __launch_bounds__(256) void cvt_x_kernel(const float* __restrict__ X)
{
    size_t i = (size_t)blockIdx.x * 256 + threadIdx.x;   // over M*C/4
    float4 v = ((const float4*)X)[i];
    __half2* d = (__half2*)(g_x + 4 * i);
    d[0] = __floats2half2_rn(v.x, v.y);
    d[1] = __floats2half2_rn(v.z, v.w);
}

// ---------------------------------------------------------------------------
// Prepass 2: W fp32 [k][n] -> transposed fp16 [w][n][k]
// ---------------------------------------------------------------------------
__global__ __launch_bounds__(256) void cvt_w_kernel(const float* __restrict__ Wq,
                                                    const float* __restrict__ Wk,
                                                    const float* __restrict__ Wv)
{
    int i = blockIdx.x * 256 + threadIdx.x;     // < 3*384*384
    int w = i / (CDIM * HDIM);
    int r = i - w * (CDIM * HDIM);
    int k = r / HDIM;
    int n = r - k * HDIM;
    const float* W = (w == 0) ? Wq : ((w == 1) ? Wk : Wv);
    g_w[((size_t)w * HDIM + n) * CDIM + k] = __float2half_rn(W[(size_t)k * HDIM + n]);
}

// ---------------------------------------------------------------------------
// Kernel: QKV GEMM via fp16 mma.sync, single-term. CTA 128x128, K chunks of
// 64, symmetric double-buffering, 2 CTAs/SM.
// Smem: stage = A(18432) + B(18432); 2 stages = 73728 B.
// ---------------------------------------------------------------------------
#define ROWB   144            // padded row stride (64 fp16 = 128B data + 16 pad)
#define QTILE  (128 * ROWB)   // 18432 bytes per operand tile
#define QSTG   (2 * QTILE)    // 36864 per stage
#define QKV_SMEM_BYTES (2 * QSTG)   // 73728
#define NCHK   6

__global__ __launch_bounds__(256, 2) void qkv_mma_kernel()
{
    extern __shared__ char smem[];
    const unsigned int sb = smem_u32(smem);
    const int t    = threadIdx.x;
    const int wid  = t >> 5;
    const int lane = t & 31;

    const int nblk = blockIdx.x;           // 0..8
    const int w    = nblk / 3;             // weight select
    const int n0   = (nblk - w * 3) * 128; // col offset within weight
    const int m0   = blockIdx.y * 128;

    const __half* wsrc = g_w + (size_t)w * HDIM * CDIM;

    const int wm = (wid & 3) * 32;
    const int wn = (wid >> 2) * 64;

    const unsigned int a_lane = (unsigned)((lane & 15) * ROWB + (lane >> 4) * 16);
    const unsigned int b_lane = (unsigned)(((lane & 7) + ((lane >> 4) << 3)) * ROWB
                                           + ((lane >> 3) & 1) * 16);

    float acc[2][8][4];
    #pragma unroll
    for (int mt = 0; mt < 2; mt++)
        #pragma unroll
        for (int nt = 0; nt < 8; nt++)
            #pragma unroll
            for (int q = 0; q < 4; q++) acc[mt][nt][q] = 0.0f;

    auto load_chunk = [&](int c, int stage) {
        const unsigned int s0 = sb + (unsigned)stage * QSTG;
        #pragma unroll
        for (int it = 0; it < 4; it++) {
            int s = t + it * 256;
            int r = s >> 3, j = s & 7;
            unsigned int d = (unsigned)(r * ROWB + j * 16);
            cp16(s0 + d,         g_x + (size_t)(m0 + r) * CDIM + c * 64 + j * 8);
            cp16(s0 + QTILE + d, wsrc + (size_t)(n0 + r) * CDIM + c * 64 + j * 8);
        }
        cp_commit();
    };

    load_chunk(0, 0);
    load_chunk(1, 1);

    for (int c = 0; c < NCHK; c++) {
        if (c + 1 < NCHK) cp_wait1(); else cp_wait0();
        __syncthreads();

        const unsigned int sa = sb + (unsigned)(c & 1) * QSTG;
        const unsigned int sbb = sa + QTILE;

        #pragma unroll
        for (int kk = 0; kk < 4; kk++) {
            const unsigned int koff = kk * 32;
            unsigned int Af[2][4];
            #pragma unroll
            for (int mt = 0; mt < 2; mt++) {
                unsigned int ab = (unsigned)((wm + mt * 16) * ROWB) + koff + a_lane;
                ldsm_x4(Af[mt], sa + ab);
            }
            #pragma unroll
            for (int nt2 = 0; nt2 < 4; nt2++) {
                unsigned int bb = (unsigned)((wn + nt2 * 16) * ROWB) + koff + b_lane;
                unsigned int Bf[4];
                ldsm_x4(Bf, sbb + bb);
                #pragma unroll
                for (int mt = 0; mt < 2; mt++) {
                    mma_fp16(acc[mt][nt2 * 2 + 0], Af[mt], Bf + 0);
                    mma_fp16(acc[mt][nt2 * 2 + 1], Af[mt], Bf + 2);
                }
            }
        }
        __syncthreads();

        if (c + 2 < NCHK) load_chunk(c + 2, c & 1);
    }

    // Epilogue: fp32 acc -> fp16 q/k/v
    __half* outp = (w == 0) ? g_q : ((w == 1) ? g_k : g_v);
    #pragma unroll
    for (int mt = 0; mt < 2; mt++) {
        int r0 = m0 + wm + mt * 16 + (lane >> 2);
        #pragma unroll
        for (int nt = 0; nt < 8; nt++) {
            int cc = n0 + wn + nt * 8 + 2 * (lane & 3);
            *(__half2*)(outp + (size_t)r0 * HDIM + cc) =
                __floats2half2_rn(acc[mt][nt][0], acc[mt][nt][1]);
            *(__half2*)(outp + (size_t)(r0 + 8) * HDIM + cc) =
                __floats2half2_rn(acc[mt][nt][2], acc[mt][nt][3]);
        }
    }
}

// ---------------------------------------------------------------------------
// Kernel: causal attention, all-fp16 single-term mma.sync, 2 CTAs/SM.
// Phase A: S = QK^T (fp16).  Phase B: fp32 softmax; P -> fp16.
// Phase C: O = P V (fp16).
// Smem overlay (bytes):
//   phase A: QB [0,9216), KB [9216,46080)
//   phase B: Ps fp32 64x260 at [46080,112640); PHI fp16 64x264 at [0,33792)
//   phase C: VB at [46080,82944)
// ---------------------------------------------------------------------------
#define AT_QB   0u
#define AT_KB   9216u
#define AT_PS   46080u
#define AT_PHI  0u
#define AT_VB   46080u
#define AT_SMEM_BYTES 112640

__global__ __launch_bounds__(256, 2) void attn_mma_kernel(float* __restrict__ Out)
{
    extern __shared__ char smem[];
    const unsigned int sb = smem_u32(smem);
    const int t    = threadIdx.x;
    const int wid  = t >> 5;
    const int lane = t & 31;
    const int bq   = blockIdx.x;          // 0..3
    const int b    = blockIdx.y;          // 0..511
    const int q0   = bq * 64;
    const int Kv   = (bq + 1) * 64;       // valid keys
    const float scl = rsqrtf((float)HDIM);

    const int wm = (wid & 1) * 32;        // warp m offset (2 m-warps)
    const int wn = (wid >> 1) * 64;       // warp n offset, phase A (4 n-warps)

    const unsigned int a_lane = (unsigned)((lane & 15) * ROWB + (lane >> 4) * 16);
    const unsigned int b_lane = (unsigned)(((lane & 7) + ((lane >> 4) << 3)) * ROWB
                                           + ((lane >> 3) & 1) * 16);
    const unsigned int p_lane = (unsigned)((lane & 15) * 528 + (lane >> 4) * 16);
    const unsigned int v_lane = (unsigned)((lane & 15) * ROWB + (lane >> 4) * 16);

    // ---------------- Phase A: S = Q K^T (fp16) ----------------------------
    float sacc[2][8][4];
    #pragma unroll
    for (int mt = 0; mt < 2; mt++)
        #pragma unroll
        for (int nt = 0; nt < 8; nt++)
            #pragma unroll
            for (int q = 0; q < 4; q++) sacc[mt][nt][q] = 0.0f;

    const bool sact = (wn < Kv);

    for (int hc = 0; hc < 6; hc++) {
        // Q chunk: 64 rows x 64 cols fp16
        #pragma unroll
        for (int it = 0; it < 2; it++) {
            int s = t + it * 256;
            int r = s >> 3, j = s & 7;
            unsigned int d = (unsigned)(r * ROWB + j * 16);
            cp16(sb + AT_QB + d, g_q + (size_t)(b * SEQ + q0 + r) * HDIM + hc * 64 + j * 8);
        }
        // K chunk: Kv rows x 64 cols fp16
        #pragma unroll
        for (int it = 0; it < 8; it++) {
            int s = t + it * 256;
            int r = s >> 3, j = s & 7;
            if (r < Kv) {
                unsigned int d = (unsigned)(r * ROWB + j * 16);
                cp16(sb + AT_KB + d, g_k + (size_t)(b * SEQ + r) * HDIM + hc * 64 + j * 8);
            }
        }
        cp_commit();
        cp_wait0();
        __syncthreads();

        if (sact) {
            #pragma unroll
            for (int kk = 0; kk < 4; kk++) {
                const unsigned int koff = kk * 32;
                unsigned int Af[2][4];
                #pragma unroll
                for (int mt = 0; mt < 2; mt++) {
                    unsigned int ab = (unsigned)((wm + mt * 16) * ROWB) + koff + a_lane;
                    ldsm_x4(Af[mt], sb + AT_QB + ab);
                }
                #pragma unroll
                for (int nt2 = 0; nt2 < 4; nt2++) {
                    unsigned int bb = (unsigned)((wn + nt2 * 16) * ROWB) + koff + b_lane;
                    unsigned int Bf[4];
                    ldsm_x4(Bf, sb + AT_KB + bb);
                    #pragma unroll
                    for (int mt = 0; mt < 2; mt++) {
                        mma_fp16(sacc[mt][nt2 * 2 + 0], Af[mt], Bf + 0);
                        mma_fp16(sacc[mt][nt2 * 2 + 1], Af[mt], Bf + 2);
                    }
                }
            }
        }
        __syncthreads();
    }

    // ---------------- Phase B: scatter S, softmax, P -> fp16 ---------------
    float* Ps = (float*)(smem + AT_PS);
    #pragma unroll
    for (int mt = 0; mt < 2; mt++) {
        int r = wm + mt * 16 + (lane >> 2);
        #pragma unroll
        for (int nt = 0; nt < 8; nt++) {
            int cc = wn + nt * 8 + 2 * (lane & 3);
            *(float2*)&Ps[r * 260 + cc] =
                make_float2(sacc[mt][nt][0] * scl, sacc[mt][nt][1] * scl);
            *(float2*)&Ps[(r + 8) * 260 + cc] =
                make_float2(sacc[mt][nt][2] * scl, sacc[mt][nt][3] * scl);
        }
    }
    __syncthreads();

    {
        const int wq = wid;                 // warp handles rows wq*8 .. wq*8+7
        for (int rr = 0; rr < 8; rr++) {
            int r  = wq * 8 + rr;
            int qg = q0 + r;                // valid keys: 0..qg
            float* row = Ps + (size_t)r * 260;
            float m = -1e30f;
            for (int j = lane; j <= qg; j += 32) m = fmaxf(m, row[j]);
            #pragma unroll
            for (int off = 16; off > 0; off >>= 1)
                m = fmaxf(m, __shfl_xor_sync(0xffffffffu, m, off));
            float s = 0.0f;
            for (int j = lane; j <= qg; j += 32) {
                float e = __expf(row[j] - m);
                row[j] = e;
                s += e;
            }
            #pragma unroll
            for (int off = 16; off > 0; off >>= 1)
                s += __shfl_xor_sync(0xffffffffu, s, off);
            float inv = 1.0f / s;
            for (int j = lane; j < Kv; j += 32)
                row[j] = (j <= qg) ? row[j] * inv : 0.0f;
        }
    }
    __syncthreads();

    // P -> fp16 (reads Ps at [46080,...), writes PHI at [0,33792))
    {
        __half* Ph = (__half*)(smem + AT_PHI);
        for (int i = t; i < 64 * 256; i += 256) {
            int r = i >> 8, c = i & 255;
            Ph[r * 264 + c] = __float2half_rn(Ps[r * 260 + c]);
        }
    }
    __syncthreads();

    // ---------------- Phase C: O = P V (fp16) ------------------------------
    const int wnc = (wid >> 1) * 16;        // warp n offset within 64-col chunk
    const int nks = Kv >> 4;                // k16 steps over keys

    for (int hc = 0; hc < 6; hc++) {
        // V chunk: Kv rows x 64 cols fp16 (overlays dead Ps)
        #pragma unroll
        for (int it = 0; it < 8; it++) {
            int s = t + it * 256;
            int r = s >> 3, j = s & 7;
            if (r < Kv) {
                unsigned int d = (unsigned)(r * ROWB + j * 16);
                cp16(sb + AT_VB + d, g_v + (size_t)(b * SEQ + r) * HDIM + hc * 64 + j * 8);
            }
        }
        cp_commit();
        cp_wait0();
        __syncthreads();

        float oacc[2][2][4];
        #pragma unroll
        for (int mt = 0; mt < 2; mt++)
            #pragma unroll
            for (int nt = 0; nt < 2; nt++)
                #pragma unroll
                for (int q = 0; q < 4; q++) oacc[mt][nt][q] = 0.0f;

        for (int ks = 0; ks < nks; ks++) {
            unsigned int Phf[2][4];
            #pragma unroll
            for (int mt = 0; mt < 2; mt++) {
                unsigned int pa = (unsigned)((wm + mt * 16) * 528) + ks * 32 + p_lane;
                ldsm_x4(Phf[mt], sb + AT_PHI + pa);
            }
            unsigned int Vh[4];
            unsigned int va = (unsigned)(ks * 16 * ROWB) + (unsigned)(wnc * 2) + v_lane;
            ldsm_x4_t(Vh, sb + AT_VB + va);
            #pragma unroll
            for (int mt = 0; mt < 2; mt++) {
                #pragma unroll
                for (int nt = 0; nt < 2; nt++) {
                    mma_fp16(oacc[mt][nt], Phf[mt], Vh + nt * 2);
                }
            }
        }

        // write O chunk
        #pragma unroll
        for (int mt = 0; mt < 2; mt++) {
            int gr = b * SEQ + q0 + wm + mt * 16 + (lane >> 2);
            #pragma unroll
            for (int nt = 0; nt < 2; nt++) {
                int gc = hc * 64 + wnc + nt * 8 + 2 * (lane & 3);
                *(float2*)(Out + (size_t)gr * HDIM + gc) =
                    make_float2(oacc[mt][nt][0], oacc[mt][nt][1]);
                *(float2*)(Out + (size_t)(gr + 8) * HDIM + gc) =
                    make_float2(oacc[mt][nt][2], oacc[mt][nt][3]);
            }
        }
        __syncthreads();
    }
}

// ---------------------------------------------------------------------------
// Launch
// ---------------------------------------------------------------------------
extern "C" void kernel_launch(void* const* d_in, const int* in_sizes, int n_in,
                              void* d_out, int out_size)
{
    const float* x  = (const float*)d_in[0];
    const float* Wq = (const float*)d_in[1];
    const float* Wk = (const float*)d_in[2];
    const float* Wv = (const float*)d_in[3];
    float* out = (float*)d_out;

    cvt_x_kernel<<<(M_TOTAL * CDIM) / 1024, 256>>>(x);
    cvt_w_kernel<<<(3 * CDIM * HDIM) / 256, 256>>>(Wq, Wk, Wv);

    cudaFuncSetAttribute(qkv_mma_kernel, cudaFuncAttributeMaxDynamicSharedMemorySize,
                         QKV_SMEM_BYTES);
    qkv_mma_kernel<<<dim3(9, M_TOTAL / 128), 256, QKV_SMEM_BYTES>>>();

    cudaFuncSetAttribute(attn_mma_kernel, cudaFuncAttributeMaxDynamicSharedMemorySize,
                         AT_SMEM_BYTES);
    attn_mma_kernel<<<dim3(SEQ / 64, BATCH), 256, AT_SMEM_BYTES>>>(out);
}

// round 11
// speedup vs baseline: 5.4490x; 1.0572x over previous
#include <cuda_runtime.h>
#include <cuda_bf16.h>
#include <cuda_fp16.h>
#include <math.h>

// Problem constants
#define BATCH 512
#define SEQ   256
#define CDIM  384
#define HDIM  384
#define M_TOTAL (BATCH * SEQ)   // 131072

// ---------------------------------------------------------------------------
// Device scratch (static: runtime allocation is forbidden)
// q/k/v single fp16 (fp16 MMA is exact given fp16 inputs; quantization 1.4e-4)
// ---------------------------------------------------------------------------
__device__ __half g_q[(size_t)M_TOTAL * HDIM];
__device__ __half g_k[(size_t)M_TOTAL * HDIM];
__device__ __half g_v[(size_t)M_TOTAL * HDIM];
__device__ __half g_x[(size_t)M_TOTAL * CDIM];          // X as fp16
__device__ __half g_w[(size_t)3 * HDIM * CDIM];         // W transposed [w][n][k], fp16

// ---------------------------------------------------------------------------
// PTX helpers (portable to plain sm_103 target — NO tcgen05)
// ---------------------------------------------------------------------------
__device__ __forceinline__ unsigned int smem_u32(const void* p) {
    unsigned int a;
    asm("{ .reg .u64 t; cvta.to.shared.u64 t, %1; cvt.u32.u64 %0, t; }" : "=r"(a) : "l"(p));
    return a;
}
__device__ __forceinline__ void cp16(unsigned int dst, const void* src) {
    asm volatile("cp.async.cg.shared.global [%0], [%1], 16;" :: "r"(dst), "l"(src));
}
__device__ __forceinline__ void cp_commit() {
    asm volatile("cp.async.commit_group;" ::: "memory");
}
__device__ __forceinline__ void cp_wait0() {
    asm volatile("cp.async.wait_group 0;" ::: "memory");
}
__device__ __forceinline__ void cp_wait1() {
    asm volatile("cp.async.wait_group 1;" ::: "memory");
}
__device__ __forceinline__ void ldsm_x4(unsigned int* r, unsigned int addr) {
    asm volatile("ldmatrix.sync.aligned.m8n8.x4.shared.b16 {%0,%1,%2,%3}, [%4];"
                 : "=r"(r[0]), "=r"(r[1]), "=r"(r[2]), "=r"(r[3]) : "r"(addr));
}
__device__ __forceinline__ void ldsm_x4_t(unsigned int* r, unsigned int addr) {
    asm volatile("ldmatrix.sync.aligned.m8n8.x4.trans.shared.b16 {%0,%1,%2,%3}, [%4];"
                 : "=r"(r[0]), "=r"(r[1]), "=r"(r[2]), "=r"(r[3]) : "r"(addr));
}
__device__ __forceinline__ void mma_fp16(float* c, const unsigned int* a,
                                         const unsigned int* b) {
    asm volatile("mma.sync.aligned.m16n8k16.row.col.f32.f16.f16.f32 "
                 "{%0,%1,%2,%3}, {%4,%5,%6,%7}, {%8,%9}, {%0,%1,%2,%3};"
                 : "+f"(c[0]), "+f"(c[1]), "+f"(c[2]), "+f"(c[3])
                 : "r"(a[0]), "r"(a[1]), "r"(a[2]), "r"(a[3]), "r"(b[0]), "r"(b[1]));
}

// ---------------------------------------------------------------------------
// Prepass 1: X fp32 -> fp16
// ---------------------------------------------------------------------------
__global__ __launch_bounds__(256) void cvt_x_kernel(const float* __restrict__ X)
{
    size_t i = (size_t)blockIdx.x * 256 + threadIdx.x;   // over M*C/4
    float4 v = ((const float4*)X)[i];
    __half2* d = (__half2*)(g_x + 4 * i);
    d[0] = __floats2half2_rn(v.x, v.y);
    d[1] = __floats2half2_rn(v.z, v.w);
}

// ---------------------------------------------------------------------------
// Prepass 2: W fp32 [k][n] -> transposed fp16 [w][n][k]
// ---------------------------------------------------------------------------
__global__ __launch_bounds__(256) void cvt_w_kernel(const float* __restrict__ Wq,
                                                    const float* __restrict__ Wk,
                                                    const float* __restrict__ Wv)
{
    int i = blockIdx.x * 256 + threadIdx.x;     // < 3*384*384
    int w = i / (CDIM * HDIM);
    int r = i - w * (CDIM * HDIM);
    int k = r / HDIM;
    int n = r - k * HDIM;
    const float* W = (w == 0) ? Wq : ((w == 1) ? Wk : Wv);
    g_w[((size_t)w * HDIM + n) * CDIM + k] = __float2half_rn(W[(size_t)k * HDIM + n]);
}

// ---------------------------------------------------------------------------
// Kernel: QKV GEMM via fp16 mma.sync, single-term. CTA 128x128, K chunks of
// 64, symmetric double-buffering, 2 CTAs/SM. (unchanged from R10)
// ---------------------------------------------------------------------------
#define ROWB   144            // padded row stride (64 fp16 = 128B data + 16 pad)
#define QTILE  (128 * ROWB)   // 18432 bytes per operand tile
#define QSTG   (2 * QTILE)    // 36864 per stage
#define QKV_SMEM_BYTES (2 * QSTG)   // 73728
#define NCHK   6

__global__ __launch_bounds__(256, 2) void qkv_mma_kernel()
{
    extern __shared__ char smem[];
    const unsigned int sb = smem_u32(smem);
    const int t    = threadIdx.x;
    const int wid  = t >> 5;
    const int lane = t & 31;

    const int nblk = blockIdx.x;           // 0..8
    const int w    = nblk / 3;             // weight select
    const int n0   = (nblk - w * 3) * 128; // col offset within weight
    const int m0   = blockIdx.y * 128;

    const __half* wsrc = g_w + (size_t)w * HDIM * CDIM;

    const int wm = (wid & 3) * 32;
    const int wn = (wid >> 2) * 64;

    const unsigned int a_lane = (unsigned)((lane & 15) * ROWB + (lane >> 4) * 16);
    const unsigned int b_lane = (unsigned)(((lane & 7) + ((lane >> 4) << 3)) * ROWB
                                           + ((lane >> 3) & 1) * 16);

    float acc[2][8][4];
    #pragma unroll
    for (int mt = 0; mt < 2; mt++)
        #pragma unroll
        for (int nt = 0; nt < 8; nt++)
            #pragma unroll
            for (int q = 0; q < 4; q++) acc[mt][nt][q] = 0.0f;

    auto load_chunk = [&](int c, int stage) {
        const unsigned int s0 = sb + (unsigned)stage * QSTG;
        #pragma unroll
        for (int it = 0; it < 4; it++) {
            int s = t + it * 256;
            int r = s >> 3, j = s & 7;
            unsigned int d = (unsigned)(r * ROWB + j * 16);
            cp16(s0 + d,         g_x + (size_t)(m0 + r) * CDIM + c * 64 + j * 8);
            cp16(s0 + QTILE + d, wsrc + (size_t)(n0 + r) * CDIM + c * 64 + j * 8);
        }
        cp_commit();
    };

    load_chunk(0, 0);
    load_chunk(1, 1);

    for (int c = 0; c < NCHK; c++) {
        if (c + 1 < NCHK) cp_wait1(); else cp_wait0();
        __syncthreads();

        const unsigned int sa = sb + (unsigned)(c & 1) * QSTG;
        const unsigned int sbb = sa + QTILE;

        #pragma unroll
        for (int kk = 0; kk < 4; kk++) {
            const unsigned int koff = kk * 32;
            unsigned int Af[2][4];
            #pragma unroll
            for (int mt = 0; mt < 2; mt++) {
                unsigned int ab = (unsigned)((wm + mt * 16) * ROWB) + koff + a_lane;
                ldsm_x4(Af[mt], sa + ab);
            }
            #pragma unroll
            for (int nt2 = 0; nt2 < 4; nt2++) {
                unsigned int bb = (unsigned)((wn + nt2 * 16) * ROWB) + koff + b_lane;
                unsigned int Bf[4];
                ldsm_x4(Bf, sbb + bb);
                #pragma unroll
                for (int mt = 0; mt < 2; mt++) {
                    mma_fp16(acc[mt][nt2 * 2 + 0], Af[mt], Bf + 0);
                    mma_fp16(acc[mt][nt2 * 2 + 1], Af[mt], Bf + 2);
                }
            }
        }
        __syncthreads();

        if (c + 2 < NCHK) load_chunk(c + 2, c & 1);
    }

    // Epilogue: fp32 acc -> fp16 q/k/v
    __half* outp = (w == 0) ? g_q : ((w == 1) ? g_k : g_v);
    #pragma unroll
    for (int mt = 0; mt < 2; mt++) {
        int r0 = m0 + wm + mt * 16 + (lane >> 2);
        #pragma unroll
        for (int nt = 0; nt < 8; nt++) {
            int cc = n0 + wn + nt * 8 + 2 * (lane & 3);
            *(__half2*)(outp + (size_t)r0 * HDIM + cc) =
                __floats2half2_rn(acc[mt][nt][0], acc[mt][nt][1]);
            *(__half2*)(outp + (size_t)(r0 + 8) * HDIM + cc) =
                __floats2half2_rn(acc[mt][nt][2], acc[mt][nt][3]);
        }
    }
}

// ---------------------------------------------------------------------------
// Kernel: causal attention, all-fp16 mma.sync, 2 CTAs/SM, DOUBLE-BUFFERED
// phase A (Q+K chunks) and phase C (V chunks).
// Smem overlay (bytes):
//   phase A stages s=0,1 at s*46080: QB +0 (9216), KB +9216 (36864) -> 92160
//   phase B: PHI fp16 64x264 at [0,33792); Ps fp32 64x260 at [40960,107520)
//   phase C: VB stages at 40960 + s*36864 -> [40960,114688)
// Total 114688 <= 116736/CTA for 2 CTAs/SM.
// ---------------------------------------------------------------------------
#define AT_STG0  0u
#define AT_STGS  46080u
#define AT_QB    0u
#define AT_KB    9216u
#define AT_PHI   0u
#define AT_PS    40960u
#define AT_VB0   40960u
#define AT_VBS   36864u
#define AT_SMEM_BYTES 114688

__global__ __launch_bounds__(256, 2) void attn_mma_kernel(float* __restrict__ Out)
{
    extern __shared__ char smem[];
    const unsigned int sb = smem_u32(smem);
    const int t    = threadIdx.x;
    const int wid  = t >> 5;
    const int lane = t & 31;
    const int bq   = blockIdx.x;          // 0..3
    const int b    = blockIdx.y;          // 0..511
    const int q0   = bq * 64;
    const int Kv   = (bq + 1) * 64;       // valid keys
    const float scl = rsqrtf((float)HDIM);

    const int wm = (wid & 1) * 32;        // warp m offset (2 m-warps)
    const int wn = (wid >> 1) * 64;       // warp n offset, phase A (4 n-warps)

    const unsigned int a_lane = (unsigned)((lane & 15) * ROWB + (lane >> 4) * 16);
    const unsigned int b_lane = (unsigned)(((lane & 7) + ((lane >> 4) << 3)) * ROWB
                                           + ((lane >> 3) & 1) * 16);
    const unsigned int p_lane = (unsigned)((lane & 15) * 528 + (lane >> 4) * 16);
    const unsigned int v_lane = (unsigned)((lane & 15) * ROWB + (lane >> 4) * 16);

    // ---------------- Phase A: S = Q K^T (fp16, double-buffered) -----------
    float sacc[2][8][4];
    #pragma unroll
    for (int mt = 0; mt < 2; mt++)
        #pragma unroll
        for (int nt = 0; nt < 8; nt++)
            #pragma unroll
            for (int q = 0; q < 4; q++) sacc[mt][nt][q] = 0.0f;

    const bool sact = (wn < Kv);

    auto load_qk = [&](int hc, int stg) {
        const unsigned int s0 = sb + (unsigned)stg * AT_STGS;
        #pragma unroll
        for (int it = 0; it < 2; it++) {
            int s = t + it * 256;
            int r = s >> 3, j = s & 7;
            unsigned int d = (unsigned)(r * ROWB + j * 16);
            cp16(s0 + AT_QB + d, g_q + (size_t)(b * SEQ + q0 + r) * HDIM + hc * 64 + j * 8);
        }
        #pragma unroll
        for (int it = 0; it < 8; it++) {
            int s = t + it * 256;
            int r = s >> 3, j = s & 7;
            if (r < Kv) {
                unsigned int d = (unsigned)(r * ROWB + j * 16);
                cp16(s0 + AT_KB + d, g_k + (size_t)(b * SEQ + r) * HDIM + hc * 64 + j * 8);
            }
        }
        cp_commit();
    };

    load_qk(0, 0);

    for (int hc = 0; hc < 6; hc++) {
        const int stg = hc & 1;
        if (hc + 1 < 6) load_qk(hc + 1, stg ^ 1);
        if (hc + 1 < 6) cp_wait1(); else cp_wait0();
        __syncthreads();

        if (sact) {
            const unsigned int sq = sb + (unsigned)stg * AT_STGS + AT_QB;
            const unsigned int sk = sb + (unsigned)stg * AT_STGS + AT_KB;
            #pragma unroll
            for (int kk = 0; kk < 4; kk++) {
                const unsigned int koff = kk * 32;
                unsigned int Af[2][4];
                #pragma unroll
                for (int mt = 0; mt < 2; mt++) {
                    unsigned int ab = (unsigned)((wm + mt * 16) * ROWB) + koff + a_lane;
                    ldsm_x4(Af[mt], sq + ab);
                }
                #pragma unroll
                for (int nt2 = 0; nt2 < 4; nt2++) {
                    unsigned int bb = (unsigned)((wn + nt2 * 16) * ROWB) + koff + b_lane;
                    unsigned int Bf[4];
                    ldsm_x4(Bf, sk + bb);
                    #pragma unroll
                    for (int mt = 0; mt < 2; mt++) {
                        mma_fp16(sacc[mt][nt2 * 2 + 0], Af[mt], Bf + 0);
                        mma_fp16(sacc[mt][nt2 * 2 + 1], Af[mt], Bf + 2);
                    }
                }
            }
        }
        __syncthreads();
    }

    // ---------------- Phase B: scatter S, softmax, P -> fp16 ---------------
    float* Ps = (float*)(smem + AT_PS);
    #pragma unroll
    for (int mt = 0; mt < 2; mt++) {
        int r = wm + mt * 16 + (lane >> 2);
        #pragma unroll
        for (int nt = 0; nt < 8; nt++) {
            int cc = wn + nt * 8 + 2 * (lane & 3);
            *(float2*)&Ps[r * 260 + cc] =
                make_float2(sacc[mt][nt][0] * scl, sacc[mt][nt][1] * scl);
            *(float2*)&Ps[(r + 8) * 260 + cc] =
                make_float2(sacc[mt][nt][2] * scl, sacc[mt][nt][3] * scl);
        }
    }
    __syncthreads();

    {
        const int wq = wid;                 // warp handles rows wq*8 .. wq*8+7
        for (int rr = 0; rr < 8; rr++) {
            int r  = wq * 8 + rr;
            int qg = q0 + r;                // valid keys: 0..qg
            float* row = Ps + (size_t)r * 260;
            float m = -1e30f;
            for (int j = lane; j <= qg; j += 32) m = fmaxf(m, row[j]);
            #pragma unroll
            for (int off = 16; off > 0; off >>= 1)
                m = fmaxf(m, __shfl_xor_sync(0xffffffffu, m, off));
            float s = 0.0f;
            for (int j = lane; j <= qg; j += 32) {
                float e = __expf(row[j] - m);
                row[j] = e;
                s += e;
            }
            #pragma unroll
            for (int off = 16; off > 0; off >>= 1)
                s += __shfl_xor_sync(0xffffffffu, s, off);
            float inv = 1.0f / s;
            for (int j = lane; j < Kv; j += 32)
                row[j] = (j <= qg) ? row[j] * inv : 0.0f;
        }
    }
    __syncthreads();

    // P -> fp16 (reads Ps at [40960,...), writes PHI at [0,33792))
    {
        __half* Ph = (__half*)(smem + AT_PHI);
        for (int i = t; i < 64 * 256; i += 256) {
            int r = i >> 8, c = i & 255;
            Ph[r * 264 + c] = __float2half_rn(Ps[r * 260 + c]);
        }
    }
    __syncthreads();

    // ---------------- Phase C: O = P V (fp16, double-buffered V) -----------
    const int wnc = (wid >> 1) * 16;        // warp n offset within 64-col chunk
    const int nks = Kv >> 4;                // k16 steps over keys

    auto load_v = [&](int hc, int stg) {
        const unsigned int v0 = sb + AT_VB0 + (unsigned)stg * AT_VBS;
        #pragma unroll
        for (int it = 0; it < 8; it++) {
            int s = t + it * 256;
            int r = s >> 3, j = s & 7;
            if (r < Kv) {
                unsigned int d = (unsigned)(r * ROWB + j * 16);
                cp16(v0 + d, g_v + (size_t)(b * SEQ + r) * HDIM + hc * 64 + j * 8);
            }
        }
        cp_commit();
    };

    load_v(0, 0);

    for (int hc = 0; hc < 6; hc++) {
        const int stg = hc & 1;
        if (hc + 1 < 6) load_v(hc + 1, stg ^ 1);
        if (hc + 1 < 6) cp_wait1(); else cp_wait0();
        __syncthreads();

        const unsigned int sv = sb + AT_VB0 + (unsigned)stg * AT_VBS;

        float oacc[2][2][4];
        #pragma unroll
        for (int mt = 0; mt < 2; mt++)
            #pragma unroll
            for (int nt = 0; nt < 2; nt++)
                #pragma unroll
                for (int q = 0; q < 4; q++) oacc[mt][nt][q] = 0.0f;

        for (int ks = 0; ks < nks; ks++) {
            unsigned int Phf[2][4];
            #pragma unroll
            for (int mt = 0; mt < 2; mt++) {
                unsigned int pa = (unsigned)((wm + mt * 16) * 528) + ks * 32 + p_lane;
                ldsm_x4(Phf[mt], sb + AT_PHI + pa);
            }
            unsigned int Vh[4];
            unsigned int va = (unsigned)(ks * 16 * ROWB) + (unsigned)(wnc * 2) + v_lane;
            ldsm_x4_t(Vh, sv + va);
            #pragma unroll
            for (int mt = 0; mt < 2; mt++) {
                #pragma unroll
                for (int nt = 0; nt < 2; nt++) {
                    mma_fp16(oacc[mt][nt], Phf[mt], Vh + nt * 2);
                }
            }
        }

        // write O chunk
        #pragma unroll
        for (int mt = 0; mt < 2; mt++) {
            int gr = b * SEQ + q0 + wm + mt * 16 + (lane >> 2);
            #pragma unroll
            for (int nt = 0; nt < 2; nt++) {
                int gc = hc * 64 + wnc + nt * 8 + 2 * (lane & 3);
                *(float2*)(Out + (size_t)gr * HDIM + gc) =
                    make_float2(oacc[mt][nt][0], oacc[mt][nt][1]);
                *(float2*)(Out + (size_t)(gr + 8) * HDIM + gc) =
                    make_float2(oacc[mt][nt][2], oacc[mt][nt][3]);
            }
        }
        __syncthreads();
    }
}

// ---------------------------------------------------------------------------
// Launch
// ---------------------------------------------------------------------------
extern "C" void kernel_launch(void* const* d_in, const int* in_sizes, int n_in,
                              void* d_out, int out_size)
{
    const float* x  = (const float*)d_in[0];
    const float* Wq = (const float*)d_in[1];
    const float* Wk = (const float*)d_in[2];
    const float* Wv = (const float*)d_in[3];
    float* out = (float*)d_out;

    cvt_x_kernel<<<(M_TOTAL * CDIM) / 1024, 256>>>(x);
    cvt_w_kernel<<<(3 * CDIM * HDIM) / 256, 256>>>(Wq, Wk, Wv);

    cudaFuncSetAttribute(qkv_mma_kernel, cudaFuncAttributeMaxDynamicSharedMemorySize,
                         QKV_SMEM_BYTES);
    qkv_mma_kernel<<<dim3(9, M_TOTAL / 128), 256, QKV_SMEM_BYTES>>>();

    cudaFuncSetAttribute(attn_mma_kernel, cudaFuncAttributeMaxDynamicSharedMemorySize,
                         AT_SMEM_BYTES);
    attn_mma_kernel<<<dim3(SEQ / 64, BATCH), 256, AT_SMEM_BYTES>>>(out);
}

// round 12
// speedup vs baseline: 5.4499x; 1.0001x over previous
#include <cuda_runtime.h>
#include <cuda_bf16.h>
#include <cuda_fp16.h>
#include <math.h>

// Problem constants
#define BATCH 512
#define SEQ   256
#define CDIM  384
#define HDIM  384
#define M_TOTAL (BATCH * SEQ)   // 131072

// ---------------------------------------------------------------------------
// Device scratch (static: runtime allocation is forbidden)
// q/k/v single fp16 (fp16 MMA is exact given fp16 inputs; quantization 1.4e-4)
// ---------------------------------------------------------------------------
__device__ __half g_q[(size_t)M_TOTAL * HDIM];
__device__ __half g_k[(size_t)M_TOTAL * HDIM];
__device__ __half g_v[(size_t)M_TOTAL * HDIM];
__device__ __half g_x[(size_t)M_TOTAL * CDIM];          // X as fp16
__device__ __half g_w[(size_t)3 * HDIM * CDIM];         // W transposed [w][n][k], fp16

// ---------------------------------------------------------------------------
// PTX helpers (portable to plain sm_103 target — NO tcgen05)
// ---------------------------------------------------------------------------
__device__ __forceinline__ unsigned int smem_u32(const void* p) {
    unsigned int a;
    asm("{ .reg .u64 t; cvta.to.shared.u64 t, %1; cvt.u32.u64 %0, t; }" : "=r"(a) : "l"(p));
    return a;
}
__device__ __forceinline__ void cp16(unsigned int dst, const void* src) {
    asm volatile("cp.async.cg.shared.global [%0], [%1], 16;" :: "r"(dst), "l"(src));
}
__device__ __forceinline__ void cp_commit() {
    asm volatile("cp.async.commit_group;" ::: "memory");
}
__device__ __forceinline__ void cp_wait0() {
    asm volatile("cp.async.wait_group 0;" ::: "memory");
}
__device__ __forceinline__ void cp_wait1() {
    asm volatile("cp.async.wait_group 1;" ::: "memory");
}
__device__ __forceinline__ void ldsm_x4(unsigned int* r, unsigned int addr) {
    asm volatile("ldmatrix.sync.aligned.m8n8.x4.shared.b16 {%0,%1,%2,%3}, [%4];"
                 : "=r"(r[0]), "=r"(r[1]), "=r"(r[2]), "=r"(r[3]) : "r"(addr));
}
__device__ __forceinline__ void ldsm_x4_t(unsigned int* r, unsigned int addr) {
    asm volatile("ldmatrix.sync.aligned.m8n8.x4.trans.shared.b16 {%0,%1,%2,%3}, [%4];"
                 : "=r"(r[0]), "=r"(r[1]), "=r"(r[2]), "=r"(r[3]) : "r"(addr));
}
__device__ __forceinline__ void mma_fp16(float* c, const unsigned int* a,
                                         const unsigned int* b) {
    asm volatile("mma.sync.aligned.m16n8k16.row.col.f32.f16.f16.f32 "
                 "{%0,%1,%2,%3}, {%4,%5,%6,%7}, {%8,%9}, {%0,%1,%2,%3};"
                 : "+f"(c[0]), "+f"(c[1]), "+f"(c[2]), "+f"(c[3])
                 : "r"(a[0]), "r"(a[1]), "r"(a[2]), "r"(a[3]), "r"(b[0]), "r"(b[1]));
}

// ---------------------------------------------------------------------------
// Prepass 1: X fp32 -> fp16
// ---------------------------------------------------------------------------
__global__ __launch_bounds__(256) void cvt_x_kernel(const float* __restrict__ X)
{
    size_t i = (size_t)blockIdx.x * 256 + threadIdx.x;   // over M*C/4
    float4 v = ((const float4*)X)[i];
    __half2* d = (__half2*)(g_x + 4 * i);
    d[0] = __floats2half2_rn(v.x, v.y);
    d[1] = __floats2half2_rn(v.z, v.w);
}

// ---------------------------------------------------------------------------
// Prepass 2: W fp32 [k][n] -> transposed fp16 [w][n][k]
// ---------------------------------------------------------------------------
__global__ __launch_bounds__(256) void cvt_w_kernel(const float* __restrict__ Wq,
                                                    const float* __restrict__ Wk,
                                                    const float* __restrict__ Wv)
{
    int i = blockIdx.x * 256 + threadIdx.x;     // < 3*384*384
    int w = i / (CDIM * HDIM);
    int r = i - w * (CDIM * HDIM);
    int k = r / HDIM;
    int n = r - k * HDIM;
    const float* W = (w == 0) ? Wq : ((w == 1) ? Wk : Wv);
    g_w[((size_t)w * HDIM + n) * CDIM + k] = __float2half_rn(W[(size_t)k * HDIM + n]);
}

// ---------------------------------------------------------------------------
// Kernel: QKV GEMM via fp16 mma.sync. CTA 128x128, K chunks of 64,
// THREE-stage pipeline, ONE sync per chunk (load for c+2 issues right after
// the top sync; stage (c+2)%3 was consumed at iter c-1), 2 CTAs/SM.
// ---------------------------------------------------------------------------
#define ROWB   144            // padded row stride (64 fp16 = 128B data + 16 pad)
#define QTILE  (128 * ROWB)   // 18432 bytes per operand tile
#define QSTG   (2 * QTILE)    // 36864 per stage
#define QKV_SMEM_BYTES (3 * QSTG)   // 110592
#define NCHK   6

__global__ __launch_bounds__(256, 2) void qkv_mma_kernel()
{
    extern __shared__ char smem[];
    const unsigned int sb = smem_u32(smem);
    const int t    = threadIdx.x;
    const int wid  = t >> 5;
    const int lane = t & 31;

    const int nblk = blockIdx.x;           // 0..8
    const int w    = nblk / 3;             // weight select
    const int n0   = (nblk - w * 3) * 128; // col offset within weight
    const int m0   = blockIdx.y * 128;

    const __half* wsrc = g_w + (size_t)w * HDIM * CDIM;

    const int wm = (wid & 3) * 32;
    const int wn = (wid >> 2) * 64;

    const unsigned int a_lane = (unsigned)((lane & 15) * ROWB + (lane >> 4) * 16);
    const unsigned int b_lane = (unsigned)(((lane & 7) + ((lane >> 4) << 3)) * ROWB
                                           + ((lane >> 3) & 1) * 16);

    float acc[2][8][4];
    #pragma unroll
    for (int mt = 0; mt < 2; mt++)
        #pragma unroll
        for (int nt = 0; nt < 8; nt++)
            #pragma unroll
            for (int q = 0; q < 4; q++) acc[mt][nt][q] = 0.0f;

    auto load_chunk = [&](int c, int stage) {
        const unsigned int s0 = sb + (unsigned)stage * QSTG;
        #pragma unroll
        for (int it = 0; it < 4; it++) {
            int s = t + it * 256;
            int r = s >> 3, j = s & 7;
            unsigned int d = (unsigned)(r * ROWB + j * 16);
            cp16(s0 + d,         g_x + (size_t)(m0 + r) * CDIM + c * 64 + j * 8);
            cp16(s0 + QTILE + d, wsrc + (size_t)(n0 + r) * CDIM + c * 64 + j * 8);
        }
        cp_commit();
    };

    load_chunk(0, 0);
    load_chunk(1, 1);

    for (int c = 0; c < NCHK; c++) {
        if (c + 1 < NCHK) cp_wait1(); else cp_wait0();
        __syncthreads();

        if (c + 2 < NCHK) load_chunk(c + 2, (c + 2) % 3);

        const unsigned int sa = sb + (unsigned)(c % 3) * QSTG;
        const unsigned int sbb = sa + QTILE;

        #pragma unroll
        for (int kk = 0; kk < 4; kk++) {
            const unsigned int koff = kk * 32;
            unsigned int Af[2][4];
            #pragma unroll
            for (int mt = 0; mt < 2; mt++) {
                unsigned int ab = (unsigned)((wm + mt * 16) * ROWB) + koff + a_lane;
                ldsm_x4(Af[mt], sa + ab);
            }
            #pragma unroll
            for (int nt2 = 0; nt2 < 4; nt2++) {
                unsigned int bb = (unsigned)((wn + nt2 * 16) * ROWB) + koff + b_lane;
                unsigned int Bf[4];
                ldsm_x4(Bf, sbb + bb);
                #pragma unroll
                for (int mt = 0; mt < 2; mt++) {
                    mma_fp16(acc[mt][nt2 * 2 + 0], Af[mt], Bf + 0);
                    mma_fp16(acc[mt][nt2 * 2 + 1], Af[mt], Bf + 2);
                }
            }
        }
        // no trailing sync: next iteration's top sync orders buffer reuse
    }

    // Epilogue: fp32 acc -> fp16 q/k/v
    __half* outp = (w == 0) ? g_q : ((w == 1) ? g_k : g_v);
    #pragma unroll
    for (int mt = 0; mt < 2; mt++) {
        int r0 = m0 + wm + mt * 16 + (lane >> 2);
        #pragma unroll
        for (int nt = 0; nt < 8; nt++) {
            int cc = n0 + wn + nt * 8 + 2 * (lane & 3);
            *(__half2*)(outp + (size_t)r0 * HDIM + cc) =
                __floats2half2_rn(acc[mt][nt][0], acc[mt][nt][1]);
            *(__half2*)(outp + (size_t)(r0 + 8) * HDIM + cc) =
                __floats2half2_rn(acc[mt][nt][2], acc[mt][nt][3]);
        }
    }
}

// ---------------------------------------------------------------------------
// Kernel: causal attention, all-fp16 mma.sync, 2 CTAs/SM, double-buffered
// phases A and C. Phase A uses BALANCED warp partitioning: the valid key
// range [0,Kv) is split evenly across the 4 n-warp-groups (nkb = bq+1
// 16-col subtiles each), so all 8 warps are always active.
// Smem overlay (bytes):
//   phase A stages s=0,1 at s*46080: QB +0 (9216), KB +9216 (36864) -> 92160
//   phase B: PHI fp16 64x264 at [0,33792); Ps fp32 64x260 at [40960,107520)
//   phase C: VB stages at 40960 + s*36864 -> [40960,114688)
// ---------------------------------------------------------------------------
#define AT_STGS  46080u
#define AT_QB    0u
#define AT_KB    9216u
#define AT_PHI   0u
#define AT_PS    40960u
#define AT_VB0   40960u
#define AT_VBS   36864u
#define AT_SMEM_BYTES 114688

__global__ __launch_bounds__(256, 2) void attn_mma_kernel(float* __restrict__ Out)
{
    extern __shared__ char smem[];
    const unsigned int sb = smem_u32(smem);
    const int t    = threadIdx.x;
    const int wid  = t >> 5;
    const int lane = t & 31;
    const int bq   = blockIdx.x;          // 0..3
    const int b    = blockIdx.y;          // 0..511
    const int q0   = bq * 64;
    const int nkb  = bq + 1;              // 16-col subtiles per n-warp-group
    const int Kv   = nkb * 64;            // valid keys
    const float scl = rsqrtf((float)HDIM);

    const int wm  = (wid & 1) * 32;       // warp m offset (2 m-warps)
    const int wng = wid >> 1;             // n-warp-group 0..3
    const int wn  = wng * 16 * nkb;       // warp col base (balanced split)

    const unsigned int a_lane = (unsigned)((lane & 15) * ROWB + (lane >> 4) * 16);
    const unsigned int b_lane = (unsigned)(((lane & 7) + ((lane >> 4) << 3)) * ROWB
                                           + ((lane >> 3) & 1) * 16);
    const unsigned int p_lane = (unsigned)((lane & 15) * 528 + (lane >> 4) * 16);
    const unsigned int v_lane = (unsigned)((lane & 15) * ROWB + (lane >> 4) * 16);

    // ---------------- Phase A: S = Q K^T (fp16, double-buffered, balanced) --
    float sacc[2][8][4];
    #pragma unroll
    for (int mt = 0; mt < 2; mt++)
        #pragma unroll
        for (int nt = 0; nt < 8; nt++)
            #pragma unroll
            for (int q = 0; q < 4; q++) sacc[mt][nt][q] = 0.0f;

    auto load_qk = [&](int hc, int stg) {
        const unsigned int s0 = sb + (unsigned)stg * AT_STGS;
        #pragma unroll
        for (int it = 0; it < 2; it++) {
            int s = t + it * 256;
            int r = s >> 3, j = s & 7;
            unsigned int d = (unsigned)(r * ROWB + j * 16);
            cp16(s0 + AT_QB + d, g_q + (size_t)(b * SEQ + q0 + r) * HDIM + hc * 64 + j * 8);
        }
        #pragma unroll
        for (int it = 0; it < 8; it++) {
            int s = t + it * 256;
            int r = s >> 3, j = s & 7;
            if (r < Kv) {
                unsigned int d = (unsigned)(r * ROWB + j * 16);
                cp16(s0 + AT_KB + d, g_k + (size_t)(b * SEQ + r) * HDIM + hc * 64 + j * 8);
            }
        }
        cp_commit();
    };

    load_qk(0, 0);

    for (int hc = 0; hc < 6; hc++) {
        const int stg = hc & 1;
        if (hc + 1 < 6) load_qk(hc + 1, stg ^ 1);
        if (hc + 1 < 6) cp_wait1(); else cp_wait0();
        __syncthreads();

        {
            const unsigned int sq = sb + (unsigned)stg * AT_STGS + AT_QB;
            const unsigned int sk = sb + (unsigned)stg * AT_STGS + AT_KB;
            #pragma unroll
            for (int kk = 0; kk < 4; kk++) {
                const unsigned int koff = kk * 32;
                unsigned int Af[2][4];
                #pragma unroll
                for (int mt = 0; mt < 2; mt++) {
                    unsigned int ab = (unsigned)((wm + mt * 16) * ROWB) + koff + a_lane;
                    ldsm_x4(Af[mt], sq + ab);
                }
                #pragma unroll
                for (int nt2 = 0; nt2 < 4; nt2++) {
                    if (nt2 < nkb) {   // CTA-uniform guard; sacc stays static
                        unsigned int bb = (unsigned)((wn + nt2 * 16) * ROWB) + koff + b_lane;
                        unsigned int Bf[4];
                        ldsm_x4(Bf, sk + bb);
                        #pragma unroll
                        for (int mt = 0; mt < 2; mt++) {
                            mma_fp16(sacc[mt][nt2 * 2 + 0], Af[mt], Bf + 0);
                            mma_fp16(sacc[mt][nt2 * 2 + 1], Af[mt], Bf + 2);
                        }
                    }
                }
            }
        }
        __syncthreads();
    }

    // ---------------- Phase B: scatter S, softmax, P -> fp16 ---------------
    float* Ps = (float*)(smem + AT_PS);
    #pragma unroll
    for (int mt = 0; mt < 2; mt++) {
        int r = wm + mt * 16 + (lane >> 2);
        #pragma unroll
        for (int nt2 = 0; nt2 < 4; nt2++) {
            if (nt2 < nkb) {
                #pragma unroll
                for (int h = 0; h < 2; h++) {
                    int cc = wn + nt2 * 16 + h * 8 + 2 * (lane & 3);
                    int nt = nt2 * 2 + h;
                    *(float2*)&Ps[r * 260 + cc] =
                        make_float2(sacc[mt][nt][0] * scl, sacc[mt][nt][1] * scl);
                    *(float2*)&Ps[(r + 8) * 260 + cc] =
                        make_float2(sacc[mt][nt][2] * scl, sacc[mt][nt][3] * scl);
                }
            }
        }
    }
    __syncthreads();

    {
        const int wq = wid;                 // warp handles rows wq*8 .. wq*8+7
        for (int rr = 0; rr < 8; rr++) {
            int r  = wq * 8 + rr;
            int qg = q0 + r;                // valid keys: 0..qg
            float* row = Ps + (size_t)r * 260;
            float m = -1e30f;
            for (int j = lane; j <= qg; j += 32) m = fmaxf(m, row[j]);
            #pragma unroll
            for (int off = 16; off > 0; off >>= 1)
                m = fmaxf(m, __shfl_xor_sync(0xffffffffu, m, off));
            float s = 0.0f;
            for (int j = lane; j <= qg; j += 32) {
                float e = __expf(row[j] - m);
                row[j] = e;
                s += e;
            }
            #pragma unroll
            for (int off = 16; off > 0; off >>= 1)
                s += __shfl_xor_sync(0xffffffffu, s, off);
            float inv = 1.0f / s;
            for (int j = lane; j < Kv; j += 32)
                row[j] = (j <= qg) ? row[j] * inv : 0.0f;
        }
    }
    __syncthreads();

    // P -> fp16 (only valid cols < Kv are ever consumed in phase C)
    {
        __half* Ph = (__half*)(smem + AT_PHI);
        for (int i = t; i < 64 * 256; i += 256) {
            int r = i >> 8, c = i & 255;
            Ph[r * 264 + c] = (c < Kv) ? __float2half_rn(Ps[r * 260 + c]) : __half(0);
        }
    }
    __syncthreads();

    // ---------------- Phase C: O = P V (fp16, double-buffered V) -----------
    const int wnc = (wid >> 1) * 16;        // warp n offset within 64-col chunk
    const int nks = Kv >> 4;                // k16 steps over keys

    auto load_v = [&](int hc, int stg) {
        const unsigned int v0 = sb + AT_VB0 + (unsigned)stg * AT_VBS;
        #pragma unroll
        for (int it = 0; it < 8; it++) {
            int s = t + it * 256;
            int r = s >> 3, j = s & 7;
            if (r < Kv) {
                unsigned int d = (unsigned)(r * ROWB + j * 16);
                cp16(v0 + d, g_v + (size_t)(b * SEQ + r) * HDIM + hc * 64 + j * 8);
            }
        }
        cp_commit();
    };

    load_v(0, 0);

    for (int hc = 0; hc < 6; hc++) {
        const int stg = hc & 1;
        if (hc + 1 < 6) load_v(hc + 1, stg ^ 1);
        if (hc + 1 < 6) cp_wait1(); else cp_wait0();
        __syncthreads();

        const unsigned int sv = sb + AT_VB0 + (unsigned)stg * AT_VBS;

        float oacc[2][2][4];
        #pragma unroll
        for (int mt = 0; mt < 2; mt++)
            #pragma unroll
            for (int nt = 0; nt < 2; nt++)
                #pragma unroll
                for (int q = 0; q < 4; q++) oacc[mt][nt][q] = 0.0f;

        for (int ks = 0; ks < nks; ks++) {
            unsigned int Phf[2][4];
            #pragma unroll
            for (int mt = 0; mt < 2; mt++) {
                unsigned int pa = (unsigned)((wm + mt * 16) * 528) + ks * 32 + p_lane;
                ldsm_x4(Phf[mt], sb + AT_PHI + pa);
            }
            unsigned int Vh[4];
            unsigned int va = (unsigned)(ks * 16 * ROWB) + (unsigned)(wnc * 2) + v_lane;
            ldsm_x4_t(Vh, sv + va);
            #pragma unroll
            for (int mt = 0; mt < 2; mt++) {
                #pragma unroll
                for (int nt = 0; nt < 2; nt++) {
                    mma_fp16(oacc[mt][nt], Phf[mt], Vh + nt * 2);
                }
            }
        }

        // write O chunk
        #pragma unroll
        for (int mt = 0; mt < 2; mt++) {
            int gr = b * SEQ + q0 + wm + mt * 16 + (lane >> 2);
            #pragma unroll
            for (int nt = 0; nt < 2; nt++) {
                int gc = hc * 64 + wnc + nt * 8 + 2 * (lane & 3);
                *(float2*)(Out + (size_t)gr * HDIM + gc) =
                    make_float2(oacc[mt][nt][0], oacc[mt][nt][1]);
                *(float2*)(Out + (size_t)(gr + 8) * HDIM + gc) =
                    make_float2(oacc[mt][nt][2], oacc[mt][nt][3]);
            }
        }
        __syncthreads();
    }
}

// ---------------------------------------------------------------------------
// Launch
// ---------------------------------------------------------------------------
extern "C" void kernel_launch(void* const* d_in, const int* in_sizes, int n_in,
                              void* d_out, int out_size)
{
    const float* x  = (const float*)d_in[0];
    const float* Wq = (const float*)d_in[1];
    const float* Wk = (const float*)d_in[2];
    const float* Wv = (const float*)d_in[3];
    float* out = (float*)d_out;

    cvt_x_kernel<<<(M_TOTAL * CDIM) / 1024, 256>>>(x);
    cvt_w_kernel<<<(3 * CDIM * HDIM) / 256, 256>>>(Wq, Wk, Wv);

    cudaFuncSetAttribute(qkv_mma_kernel, cudaFuncAttributeMaxDynamicSharedMemorySize,
                         QKV_SMEM_BYTES);
    qkv_mma_kernel<<<dim3(9, M_TOTAL / 128), 256, QKV_SMEM_BYTES>>>();

    cudaFuncSetAttribute(attn_mma_kernel, cudaFuncAttributeMaxDynamicSharedMemorySize,
                         AT_SMEM_BYTES);
    attn_mma_kernel<<<dim3(SEQ / 64, BATCH), 256, AT_SMEM_BYTES>>>(out);
}